// round 6
// baseline (speedup 1.0000x reference)
#include <cuda_runtime.h>
#include <cstdint>
#include <math.h>

#define HIDDEN 2048
#define NHEADS 16
#define HDIM 128
#define FFDIM 5632
#define BATCHN 2
#define SEQ 2048
#define NTOK (BATCHN*SEQ)   // 4096

// ---------------- scratch (device globals: no allocation allowed) ----------------
__device__ float g_xnorm[NTOK*HIDDEN];
__device__ float g_q[NTOK*HIDDEN];
__device__ float g_k[NTOK*HIDDEN];
__device__ float g_v[NTOK*HIDDEN];
__device__ float g_attnout[NTOK*HIDDEN];
__device__ float g_h[NTOK*HIDDEN];
__device__ float g_ffn[NTOK*HIDDEN];
__device__ float g_g1[(size_t)NTOK*FFDIM];
__device__ float g_g3[(size_t)NTOK*FFDIM];
__device__ float g_invf[64];
// tf32-rounded weights
__device__ float g_wq[HIDDEN*HIDDEN];
__device__ float g_wk[HIDDEN*HIDDEN];
__device__ float g_wv[HIDDEN*HIDDEN];
__device__ float g_wo[HIDDEN*HIDDEN];
__device__ float g_w1[(size_t)HIDDEN*FFDIM];
__device__ float g_w3[(size_t)HIDDEN*FFDIM];
__device__ float g_w2[(size_t)FFDIM*HIDDEN];

// ---------------- helpers ----------------
__device__ __forceinline__ float rna_tf32(float x){
    unsigned r; asm("cvt.rna.tf32.f32 %0, %1;" : "=r"(r) : "f"(x));
    return __uint_as_float(r);
}
__device__ __forceinline__ unsigned smem_u32(const void* p){
    return (unsigned)__cvta_generic_to_shared(p);
}
__device__ __forceinline__ void cp16(unsigned s, const void* g){
    asm volatile("cp.async.cg.shared.global [%0], [%1], 16;\n" :: "r"(s), "l"(g));
}
#define CP_COMMIT() asm volatile("cp.async.commit_group;\n")
#define CP_WAIT(n)  asm volatile("cp.async.wait_group %0;\n" :: "n"(n))

__device__ __forceinline__ void mma_tf32(float c[4],
        unsigned a0, unsigned a1, unsigned a2, unsigned a3,
        unsigned b0, unsigned b1){
    asm volatile("mma.sync.aligned.m16n8k8.row.col.f32.tf32.tf32.f32 "
        "{%0,%1,%2,%3},{%4,%5,%6,%7},{%8,%9},{%0,%1,%2,%3};\n"
        : "+f"(c[0]), "+f"(c[1]), "+f"(c[2]), "+f"(c[3])
        : "r"(a0), "r"(a1), "r"(a2), "r"(a3), "r"(b0), "r"(b1));
}

__device__ __forceinline__ float warpReduceSum(float v){
    #pragma unroll
    for (int o=16;o;o>>=1) v += __shfl_xor_sync(0xffffffffu, v, o);
    return v;
}
__device__ float blockReduceSum(float v){   // 256 threads
    __shared__ float s[8]; __shared__ float tot;
    int lane = threadIdx.x & 31, w = threadIdx.x >> 5;
    v = warpReduceSum(v);
    if (!lane) s[w] = v;
    __syncthreads();
    if (w == 0){
        float t = (lane < 8) ? s[lane] : 0.f;
        t = warpReduceSum(t);
        if (!lane) tot = t;
    }
    __syncthreads();
    return tot;
}

// ---------------- tf32 GEMM: C[M,N] = A[M,K] @ B[K,N] (+ Res) ----------------
// Tiles: BM=128, BN=128, BK=32; 4 warps of 64x64 (128 threads); 3 CTAs/SM.
// 64x64 warp tile: 32 fragment LDS per 32 MMAs = 128 B crossbar per MMA.
#define ASTR 36
#define ASZG (128*ASTR)          // 4608 floats per buffer
#define BSZG (32*136)            // 4352 floats per buffer
#define SMEM_N ((2*ASZG + 2*BSZG)*4)   // 71680 B

__global__ void __launch_bounds__(128, 3)
gemm_tf32(const float* __restrict__ A, int lda,
          const float* __restrict__ B, int ldb,
          float* __restrict__ C, int ldc,
          const float* __restrict__ Res,
          int K, int npm, int npn, int roundOut,
          const int* __restrict__ pos, int doRope)
{
    extern __shared__ float sm[];

    // grouped rasterization for L2 reuse
    int pid = blockIdx.x;
    const int GROUP = 8;
    int npg = GROUP * npn;
    int gid = pid / npg;
    int firstm = gid * GROUP;
    int gsz = min(GROUP, npm - firstm);
    int pm = firstm + (pid % npg) % gsz;
    int pn = (pid % npg) / gsz;
    int m0 = pm * 128, n0 = pn * 128;

    int KT = K / 32;
    int tid = threadIdx.x;
    int wid = tid >> 5, lane = tid & 31;
    int wm = (wid & 1) * 64;
    int wn = (wid >> 1) * 64;
    int rl = lane >> 2, l3 = lane & 3;

    auto loadA = [&](int buf, int kt){
        float* s = sm + buf * ASZG;
        int c = tid & 7;
        int r0 = tid >> 3;                 // 16 rows per pass
        const float* gp = A + (long long)m0 * lda + kt * 32 + c * 4;
        #pragma unroll
        for (int w = 0; w < 8; w++){
            int row = r0 + 16 * w;
            cp16(smem_u32(s + row * ASTR + c * 4), gp + (long long)row * lda);
        }
    };
    auto loadB = [&](int buf, int kt){
        float* s = sm + 2 * ASZG + buf * BSZG;
        int c = tid & 31;
        int r0 = tid >> 5;                 // 4 rows per pass
        const float* gp = B + (long long)(kt * 32) * ldb + n0 + c * 4;
        #pragma unroll
        for (int w = 0; w < 8; w++){
            int row = r0 + 4 * w;
            cp16(smem_u32(s + row * 136 + c * 4), gp + (long long)row * ldb);
        }
    };

    float acc[4][8][4];
    #pragma unroll
    for (int i=0;i<4;i++)
        #pragma unroll
        for (int j=0;j<8;j++)
            #pragma unroll
            for (int r=0;r<4;r++) acc[i][j][r] = 0.f;

    loadA(0, 0); loadB(0, 0); CP_COMMIT();

    for (int kt = 0; kt < KT; kt++){
        int buf = kt & 1;
        if (kt + 1 < KT){
            loadA(buf ^ 1, kt + 1); loadB(buf ^ 1, kt + 1);
            CP_COMMIT();
            CP_WAIT(1);
        } else {
            CP_WAIT(0);
        }
        __syncthreads();
        const float* sa = sm + buf * ASZG;
        const float* sb = sm + 2 * ASZG + buf * BSZG;

        #pragma unroll
        for (int ks = 0; ks < 4; ks++){
            int kk = ks * 8;
            unsigned a[4][4];
            #pragma unroll
            for (int mi = 0; mi < 4; mi++){
                const float* ap = sa + (wm + mi * 16 + rl) * ASTR + kk + l3;
                a[mi][0] = __float_as_uint(ap[0]);
                a[mi][1] = __float_as_uint(ap[8 * ASTR]);
                a[mi][2] = __float_as_uint(ap[4]);
                a[mi][3] = __float_as_uint(ap[8 * ASTR + 4]);
            }
            #pragma unroll
            for (int ni = 0; ni < 8; ni++){
                const float* bp = sb + (kk + l3) * 136 + wn + ni * 8 + rl;
                unsigned b0 = __float_as_uint(bp[0]);
                unsigned b1 = __float_as_uint(bp[4 * 136]);
                #pragma unroll
                for (int mi = 0; mi < 4; mi++)
                    mma_tf32(acc[mi][ni], a[mi][0], a[mi][1], a[mi][2], a[mi][3], b0, b1);
            }
        }
        __syncthreads();
    }

    // epilogue
    #pragma unroll
    for (int mi = 0; mi < 4; mi++){
        #pragma unroll
        for (int ni = 0; ni < 8; ni++){
            int row = m0 + wm + mi * 16 + rl;
            int col = n0 + wn + ni * 8 + l3 * 2;
            float v0 = acc[mi][ni][0];
            float v1 = acc[mi][ni][1];
            float v2 = acc[mi][ni][2];
            float v3 = acc[mi][ni][3];
            if (Res){
                float2 r01 = *(const float2*)(Res + (long long)row * ldc + col);
                float2 r23 = *(const float2*)(Res + (long long)(row + 8) * ldc + col);
                v0 += r01.x; v1 += r01.y; v2 += r23.x; v3 += r23.y;
            }
            if (doRope){
                int i = (col & 127) >> 1;
                float invf = g_invf[i];
                float a0 = (float)pos[row] * invf;
                float a1 = (float)pos[row + 8] * invf;
                float s0, c0, s1, c1;
                sincosf(a0, &s0, &c0);
                sincosf(a1, &s1, &c1);
                float t0 = v0 * c0 - v1 * s0;
                float t1 = v1 * c0 + v0 * s0;
                float t2 = v2 * c1 - v3 * s1;
                float t3 = v3 * c1 + v2 * s1;
                v0 = t0; v1 = t1; v2 = t2; v3 = t3;
            }
            if (roundOut | doRope){
                v0 = rna_tf32(v0); v1 = rna_tf32(v1);
                v2 = rna_tf32(v2); v3 = rna_tf32(v3);
            }
            *(float2*)(C + (long long)row * ldc + col)       = make_float2(v0, v1);
            *(float2*)(C + (long long)(row + 8) * ldc + col) = make_float2(v2, v3);
        }
    }
}

// ---------------- flash attention (gemm-style double buffer, 64-key tiles) ----
// Per CTA: one (b,h) and one 128-row q tile. 8 warps, each owns 16 q rows.
#define KSTR 140
#define VSTR 136
#define PSTR 76
#define KTILE 64
#define FLASH_SMEM ((2*KTILE*KSTR + 2*KTILE*VSTR + 8*16*PSTR)*4)   // 180224 B

__global__ void __launch_bounds__(256, 1)
flash_attn(const float* __restrict__ Q, const float* __restrict__ K,
           const float* __restrict__ V, float* __restrict__ O,
           float alpha)
{
    extern __shared__ float sm[];
    float* sKb = sm;                        // 2 * 64*140
    float* sVb = sm + 2*KTILE*KSTR;         // 2 * 64*136
    float* sP  = sVb + 2*KTILE*VSTR;        // 8*16*76

    int z = blockIdx.y;               // b*16+h
    int b = z >> 4, h = z & 15;
    int qt = (gridDim.x - 1) - blockIdx.x;   // heavy tiles first
    int q0 = qt * 128;
    const float* Qg = Q + ((long long)b * SEQ) * HIDDEN + h * HDIM;
    const float* Kg = K + ((long long)b * SEQ) * HIDDEN + h * HDIM;
    const float* Vg = V + ((long long)b * SEQ) * HIDDEN + h * HDIM;
    float* Og = O + ((long long)b * SEQ) * HIDDEN + h * HDIM;

    int tid = threadIdx.x, wid = tid >> 5, lane = tid & 31;
    int rl = lane >> 2, l3 = lane & 3;
    int qr = q0 + wid * 16;
    float* sPw = sP + wid * 16 * PSTR;

    // Q fragments in registers (already tf32-rounded + rope'd by producer)
    unsigned qf[16][4];
    #pragma unroll
    for (int ks = 0; ks < 16; ks++){
        const float* p0 = Qg + (long long)(qr + rl) * HIDDEN + ks * 8 + l3;
        const float* p1 = Qg + (long long)(qr + rl + 8) * HIDDEN + ks * 8 + l3;
        qf[ks][0] = __float_as_uint(p0[0]);
        qf[ks][1] = __float_as_uint(p1[0]);
        qf[ks][2] = __float_as_uint(p0[4]);
        qf[ks][3] = __float_as_uint(p1[4]);
    }

    float Oa[16][4];
    #pragma unroll
    for (int ni = 0; ni < 16; ni++){
        Oa[ni][0] = 0.f; Oa[ni][1] = 0.f; Oa[ni][2] = 0.f; Oa[ni][3] = 0.f;
    }
    float m0r = -1e30f, m1r = -1e30f, l0r = 0.f, l1r = 0.f;

    // one commit group per tile: K then V (64 rows x 128 floats each)
    auto loadKV = [&](int buf, int t){
        int c = tid & 31, r0 = tid >> 5;
        const float* kp = Kg + (long long)(t * KTILE) * HIDDEN + c * 4;
        const float* vp = Vg + (long long)(t * KTILE) * HIDDEN + c * 4;
        float* dk = sKb + buf * KTILE * KSTR;
        float* dv = sVb + buf * KTILE * VSTR;
        #pragma unroll
        for (int w = 0; w < 8; w++){
            int row = r0 + 8 * w;
            cp16(smem_u32(dk + row * KSTR + c * 4), kp + (long long)row * HIDDEN);
        }
        #pragma unroll
        for (int w = 0; w < 8; w++){
            int row = r0 + 8 * w;
            cp16(smem_u32(dv + row * VSTR + c * 4), vp + (long long)row * HIDDEN);
        }
    };

    int nt = 2 * qt + 2;
    loadKV(0, 0); CP_COMMIT();

    for (int t = 0; t < nt; t++){
        int buf = t & 1;
        if (t + 1 < nt){
            loadKV(buf ^ 1, t + 1);
            CP_COMMIT();
            CP_WAIT(1);
        } else {
            CP_WAIT(0);
        }
        __syncthreads();
        const float* cK = sKb + buf * KTILE * KSTR;
        const float* cV = sVb + buf * KTILE * VSTR;
        int diag = (t >= 2 * qt);
        int k0 = t * KTILE;

        // S = Q @ K^T over 64 keys
        float Sa[8][4];
        #pragma unroll
        for (int ni = 0; ni < 8; ni++){
            Sa[ni][0]=0.f; Sa[ni][1]=0.f; Sa[ni][2]=0.f; Sa[ni][3]=0.f;
        }
        #pragma unroll
        for (int ks = 0; ks < 16; ks++){
            #pragma unroll
            for (int ni = 0; ni < 8; ni++){
                int n = ni * 8 + rl;
                unsigned b0 = __float_as_uint(cK[n * KSTR + ks * 8 + l3]);
                unsigned b1 = __float_as_uint(cK[n * KSTR + ks * 8 + 4 + l3]);
                mma_tf32(Sa[ni], qf[ks][0], qf[ks][1], qf[ks][2], qf[ks][3], b0, b1);
            }
        }

        // scale + causal mask + row max
        int r0g = qr + rl, r1g = qr + rl + 8;
        float mx0 = -1e30f, mx1 = -1e30f;
        #pragma unroll
        for (int ni = 0; ni < 8; ni++){
            float x0 = Sa[ni][0] * alpha, x1 = Sa[ni][1] * alpha;
            float x2 = Sa[ni][2] * alpha, x3 = Sa[ni][3] * alpha;
            if (diag){
                int kg = k0 + ni * 8 + 2 * l3;
                if (kg     > r0g) x0 = -1e30f;
                if (kg + 1 > r0g) x1 = -1e30f;
                if (kg     > r1g) x2 = -1e30f;
                if (kg + 1 > r1g) x3 = -1e30f;
            }
            Sa[ni][0]=x0; Sa[ni][1]=x1; Sa[ni][2]=x2; Sa[ni][3]=x3;
            mx0 = fmaxf(mx0, fmaxf(x0, x1));
            mx1 = fmaxf(mx1, fmaxf(x2, x3));
        }
        mx0 = fmaxf(mx0, __shfl_xor_sync(0xffffffffu, mx0, 1));
        mx0 = fmaxf(mx0, __shfl_xor_sync(0xffffffffu, mx0, 2));
        mx1 = fmaxf(mx1, __shfl_xor_sync(0xffffffffu, mx1, 1));
        mx1 = fmaxf(mx1, __shfl_xor_sync(0xffffffffu, mx1, 2));

        float mn0 = fmaxf(m0r, mx0), mn1 = fmaxf(m1r, mx1);
        float cr0 = __expf(m0r - mn0), cr1 = __expf(m1r - mn1);
        m0r = mn0; m1r = mn1;
        l0r *= cr0; l1r *= cr1;
        #pragma unroll
        for (int ni = 0; ni < 16; ni++){
            Oa[ni][0] *= cr0; Oa[ni][1] *= cr0;
            Oa[ni][2] *= cr1; Oa[ni][3] *= cr1;
        }
        float rs0 = 0.f, rs1 = 0.f;
        #pragma unroll
        for (int ni = 0; ni < 8; ni++){
            float e0 = __expf(Sa[ni][0] - mn0);
            float e1 = __expf(Sa[ni][1] - mn0);
            float e2 = __expf(Sa[ni][2] - mn1);
            float e3 = __expf(Sa[ni][3] - mn1);
            rs0 += e0 + e1; rs1 += e2 + e3;
            int colp = ni * 8 + 2 * l3;
            *(float2*)(sPw + rl * PSTR + colp)       = make_float2(rna_tf32(e0), rna_tf32(e1));
            *(float2*)(sPw + (rl + 8) * PSTR + colp) = make_float2(rna_tf32(e2), rna_tf32(e3));
        }
        rs0 += __shfl_xor_sync(0xffffffffu, rs0, 1);
        rs0 += __shfl_xor_sync(0xffffffffu, rs0, 2);
        rs1 += __shfl_xor_sync(0xffffffffu, rs1, 1);
        rs1 += __shfl_xor_sync(0xffffffffu, rs1, 2);
        l0r += rs0; l1r += rs1;
        __syncwarp();

        // O += P @ V  (64 keys => ks 0..7)
        #pragma unroll
        for (int ks = 0; ks < 8; ks++){
            unsigned a0 = __float_as_uint(sPw[rl * PSTR + ks * 8 + l3]);
            unsigned a1 = __float_as_uint(sPw[(rl + 8) * PSTR + ks * 8 + l3]);
            unsigned a2 = __float_as_uint(sPw[rl * PSTR + ks * 8 + 4 + l3]);
            unsigned a3 = __float_as_uint(sPw[(rl + 8) * PSTR + ks * 8 + 4 + l3]);
            #pragma unroll
            for (int ni = 0; ni < 16; ni++){
                unsigned b0 = __float_as_uint(cV[(ks * 8 + l3) * VSTR + ni * 8 + rl]);
                unsigned b1 = __float_as_uint(cV[(ks * 8 + 4 + l3) * VSTR + ni * 8 + rl]);
                mma_tf32(Oa[ni], a0, a1, a2, a3, b0, b1);
            }
        }
        __syncthreads();   // all warps done with cK/cV before prefetch overwrites
    }

    // normalize + write (rounded: feeds WO gemm)
    float inv0 = 1.0f / l0r, inv1 = 1.0f / l1r;
    #pragma unroll
    for (int ni = 0; ni < 16; ni++){
        int col = ni * 8 + 2 * l3;
        *(float2*)(Og + (long long)(qr + rl) * HIDDEN + col) =
            make_float2(rna_tf32(Oa[ni][0] * inv0), rna_tf32(Oa[ni][1] * inv0));
        *(float2*)(Og + (long long)(qr + rl + 8) * HIDDEN + col) =
            make_float2(rna_tf32(Oa[ni][2] * inv1), rna_tf32(Oa[ni][3] * inv1));
    }
}

// ---------------- small kernels ----------------
__global__ void round_all(const float4* s0, float4* d0, const float4* s1, float4* d1,
                          const float4* s2, float4* d2, const float4* s3, float4* d3,
                          const float4* s4, float4* d4, const float4* s5, float4* d5,
                          const float4* s6, float4* d6)
{
    int gid = blockIdx.x * blockDim.x + threadIdx.x;
    int st = gridDim.x * blockDim.x;
    if (gid < 64) g_invf[gid] = (float)exp(-(double)gid * (log(500000.0) / 64.0));
    const int NA = HIDDEN * HIDDEN / 4;          // 1048576
    const int NB = HIDDEN * FFDIM / 4;           // 2883584
    const float4* srcs[7] = {s0, s1, s2, s3, s4, s5, s6};
    float4*       dsts[7] = {d0, d1, d2, d3, d4, d5, d6};
    #pragma unroll
    for (int seg = 0; seg < 7; seg++){
        int n = (seg < 4) ? NA : NB;
        const float4* s = srcs[seg];
        float4* d = dsts[seg];
        for (int i = gid; i < n; i += st){
            float4 v = s[i];
            v.x = rna_tf32(v.x); v.y = rna_tf32(v.y);
            v.z = rna_tf32(v.z); v.w = rna_tf32(v.w);
            d[i] = v;
        }
    }
}

__global__ void rmsnorm_kernel(const float* __restrict__ X, const float* __restrict__ sc,
                               float* __restrict__ O){
    long long base = (long long)blockIdx.x * HIDDEN;
    int tid = threadIdx.x;
    float v[8]; float ss = 0.f;
    #pragma unroll
    for (int i = 0; i < 8; i++){
        v[i] = X[base + tid + i * 256];
        ss += v[i] * v[i];
    }
    ss = blockReduceSum(ss);
    float r = rsqrtf(ss * (1.0f / (float)HIDDEN) + 1e-5f);
    #pragma unroll
    for (int i = 0; i < 8; i++){
        int c = tid + i * 256;
        O[base + c] = rna_tf32(v[i] * r * sc[c]);
    }
}

__global__ void silu_mul(float4* __restrict__ a, const float4* __restrict__ b, int n4){
    int i = blockIdx.x * blockDim.x + threadIdx.x;
    int st = gridDim.x * blockDim.x;
    for (; i < n4; i += st){
        float4 x = a[i], y = b[i];
        float s0 = x.x / (1.0f + expf(-x.x));
        float s1 = x.y / (1.0f + expf(-x.y));
        float s2 = x.z / (1.0f + expf(-x.z));
        float s3 = x.w / (1.0f + expf(-x.w));
        x.x = rna_tf32(s0 * y.x); x.y = rna_tf32(s1 * y.y);
        x.z = rna_tf32(s2 * y.z); x.w = rna_tf32(s3 * y.w);
        a[i] = x;
    }
}

// ---------------- launch ----------------
extern "C" void kernel_launch(void* const* d_in, const int* in_sizes, int n_in,
                              void* d_out, int out_size)
{
    const float* x   = (const float*)d_in[0];
    const int*   pos = (const int*)d_in[1];
    // d_in[2] = mask (causal; handled analytically)
    const float* wq  = (const float*)d_in[3];
    const float* wk  = (const float*)d_in[4];
    const float* wv  = (const float*)d_in[5];
    const float* wo  = (const float*)d_in[6];
    const float* asc = (const float*)d_in[7];
    const float* fsc = (const float*)d_in[8];
    const float* w1  = (const float*)d_in[9];
    const float* w3  = (const float*)d_in[10];
    const float* w2  = (const float*)d_in[11];
    float* out = (float*)d_out;

    float *p_xn,*p_q,*p_k,*p_v,*p_ao,*p_h,*p_ffn,*p_g1,*p_g3;
    float *p_wq,*p_wk,*p_wv,*p_wo,*p_w1,*p_w3,*p_w2;
    cudaGetSymbolAddress((void**)&p_xn, g_xnorm);
    cudaGetSymbolAddress((void**)&p_q,  g_q);
    cudaGetSymbolAddress((void**)&p_k,  g_k);
    cudaGetSymbolAddress((void**)&p_v,  g_v);
    cudaGetSymbolAddress((void**)&p_ao, g_attnout);
    cudaGetSymbolAddress((void**)&p_h,  g_h);
    cudaGetSymbolAddress((void**)&p_ffn,g_ffn);
    cudaGetSymbolAddress((void**)&p_g1, g_g1);
    cudaGetSymbolAddress((void**)&p_g3, g_g3);
    cudaGetSymbolAddress((void**)&p_wq, g_wq);
    cudaGetSymbolAddress((void**)&p_wk, g_wk);
    cudaGetSymbolAddress((void**)&p_wv, g_wv);
    cudaGetSymbolAddress((void**)&p_wo, g_wo);
    cudaGetSymbolAddress((void**)&p_w1, g_w1);
    cudaGetSymbolAddress((void**)&p_w3, g_w3);
    cudaGetSymbolAddress((void**)&p_w2, g_w2);

    cudaFuncSetAttribute(gemm_tf32, cudaFuncAttributeMaxDynamicSharedMemorySize, SMEM_N);
    cudaFuncSetAttribute(flash_attn, cudaFuncAttributeMaxDynamicSharedMemorySize, FLASH_SMEM);

    // 0. round weights to tf32 (rna) + inv_freq table
    round_all<<<4096,256>>>((const float4*)wq, (float4*)p_wq,
                            (const float4*)wk, (float4*)p_wk,
                            (const float4*)wv, (float4*)p_wv,
                            (const float4*)wo, (float4*)p_wo,
                            (const float4*)w1, (float4*)p_w1,
                            (const float4*)w3, (float4*)p_w3,
                            (const float4*)w2, (float4*)p_w2);

    // 1. rmsnorm (attn)
    rmsnorm_kernel<<<NTOK,256>>>(x, asc, p_xn);

    // 2-4. Q/K/V projections (rope fused into Q,K epilogues)
    dim3 gProj(32*16, 1, 1);
    gemm_tf32<<<gProj,128,SMEM_N>>>(p_xn,HIDDEN, p_wq,HIDDEN, p_q,HIDDEN,
                                    nullptr, HIDDEN, 32,16, 0, pos, 1);
    gemm_tf32<<<gProj,128,SMEM_N>>>(p_xn,HIDDEN, p_wk,HIDDEN, p_k,HIDDEN,
                                    nullptr, HIDDEN, 32,16, 0, pos, 1);
    gemm_tf32<<<gProj,128,SMEM_N>>>(p_xn,HIDDEN, p_wv,HIDDEN, p_v,HIDDEN,
                                    nullptr, HIDDEN, 32,16, 1, nullptr, 0);

    // 5. flash attention (profiled by ncu -s 5)
    flash_attn<<<dim3(16, BATCHN*NHEADS),256,FLASH_SMEM>>>(
        p_q, p_k, p_v, p_ao, 0.08838834764831845f);

    // 6. h = x + attn_out @ wo
    gemm_tf32<<<gProj,128,SMEM_N>>>(p_ao,HIDDEN, p_wo,HIDDEN, p_h,HIDDEN,
                                    x, HIDDEN, 32,16, 0, nullptr, 0);

    // 7. rmsnorm (ffn)
    rmsnorm_kernel<<<NTOK,256>>>(p_h, fsc, p_ffn);

    // 8-9. g1 = ff @ w1 ; g3 = ff @ w3
    dim3 gFF(32*44, 1, 1);
    gemm_tf32<<<gFF,128,SMEM_N>>>(p_ffn,HIDDEN, p_w1,FFDIM, p_g1,FFDIM,
                                  nullptr, HIDDEN, 32,44, 0, nullptr, 0);
    gemm_tf32<<<gFF,128,SMEM_N>>>(p_ffn,HIDDEN, p_w3,FFDIM, p_g3,FFDIM,
                                  nullptr, HIDDEN, 32,44, 0, nullptr, 0);

    // 10. g1 = silu(g1) * g3
    silu_mul<<<4096,256>>>((float4*)p_g1, (const float4*)p_g3, (int)((size_t)NTOK*FFDIM/4));

    // 11. out = h + g1 @ w2
    gemm_tf32<<<gProj,128,SMEM_N>>>(p_g1,FFDIM, p_w2,HIDDEN, out,HIDDEN,
                                    p_h, FFDIM, 32,16, 0, nullptr, 0);
}

// round 8
// speedup vs baseline: 1.0643x; 1.0643x over previous
#include <cuda_runtime.h>
#include <cuda_fp16.h>
#include <cstdint>
#include <math.h>

#define HIDDEN 2048
#define NHEADS 16
#define HDIM 128
#define FFDIM 5632
#define BATCHN 2
#define SEQ 2048
#define NTOK (BATCHN*SEQ)   // 4096

// ---------------- scratch (device globals: no allocation allowed) ----------------
__device__ __half g_xnh[NTOK*HIDDEN];          // fp16 rmsnorm(attn) output
__device__ float  g_q[NTOK*HIDDEN];
__device__ float  g_k[NTOK*HIDDEN];
__device__ float  g_v[NTOK*HIDDEN];
__device__ __half g_aoh[NTOK*HIDDEN];          // fp16 attention output
__device__ float  g_h[NTOK*HIDDEN];
__device__ __half g_ffnh[NTOK*HIDDEN];         // fp16 rmsnorm(ffn) output
__device__ float  g_g1[(size_t)NTOK*FFDIM];
__device__ float  g_g3[(size_t)NTOK*FFDIM];
__device__ __half g_g1h[(size_t)NTOK*FFDIM];   // fp16 silu(g1)*g3
__device__ float  g_invf[64];
// fp16 TRANSPOSED weights [N, K] K-major
__device__ __half g_wq[HIDDEN*HIDDEN];
__device__ __half g_wk[HIDDEN*HIDDEN];
__device__ __half g_wv[HIDDEN*HIDDEN];
__device__ __half g_wo[HIDDEN*HIDDEN];
__device__ __half g_w1[(size_t)HIDDEN*FFDIM];
__device__ __half g_w3[(size_t)HIDDEN*FFDIM];
__device__ __half g_w2[(size_t)FFDIM*HIDDEN];

// ---------------- helpers ----------------
__device__ __forceinline__ float rna_tf32(float x){
    unsigned r; asm("cvt.rna.tf32.f32 %0, %1;" : "=r"(r) : "f"(x));
    return __uint_as_float(r);
}
__device__ __forceinline__ unsigned smem_u32(const void* p){
    return (unsigned)__cvta_generic_to_shared(p);
}
__device__ __forceinline__ void cp16(unsigned s, const void* g){
    asm volatile("cp.async.cg.shared.global [%0], [%1], 16;\n" :: "r"(s), "l"(g));
}
#define CP_COMMIT() asm volatile("cp.async.commit_group;\n")
#define CP_WAIT(n)  asm volatile("cp.async.wait_group %0;\n" :: "n"(n))

// tf32 mma (flash attention)
__device__ __forceinline__ void mma_tf32(float c[4],
        unsigned a0, unsigned a1, unsigned a2, unsigned a3,
        unsigned b0, unsigned b1){
    asm volatile("mma.sync.aligned.m16n8k8.row.col.f32.tf32.tf32.f32 "
        "{%0,%1,%2,%3},{%4,%5,%6,%7},{%8,%9},{%0,%1,%2,%3};\n"
        : "+f"(c[0]), "+f"(c[1]), "+f"(c[2]), "+f"(c[3])
        : "r"(a0), "r"(a1), "r"(a2), "r"(a3), "r"(b0), "r"(b1));
}
// fp16 mma, fp32 accumulate
__device__ __forceinline__ void mma_h(float c[4],
        unsigned a0, unsigned a1, unsigned a2, unsigned a3,
        unsigned b0, unsigned b1){
    asm volatile("mma.sync.aligned.m16n8k16.row.col.f32.f16.f16.f32 "
        "{%0,%1,%2,%3},{%4,%5,%6,%7},{%8,%9},{%0,%1,%2,%3};\n"
        : "+f"(c[0]), "+f"(c[1]), "+f"(c[2]), "+f"(c[3])
        : "r"(a0), "r"(a1), "r"(a2), "r"(a3), "r"(b0), "r"(b1));
}

__device__ __forceinline__ float warpReduceSum(float v){
    #pragma unroll
    for (int o=16;o;o>>=1) v += __shfl_xor_sync(0xffffffffu, v, o);
    return v;
}
__device__ float blockReduceSum(float v){   // 256 threads
    __shared__ float s[8]; __shared__ float tot;
    int lane = threadIdx.x & 31, w = threadIdx.x >> 5;
    v = warpReduceSum(v);
    if (!lane) s[w] = v;
    __syncthreads();
    if (w == 0){
        float t = (lane < 8) ? s[lane] : 0.f;
        t = warpReduceSum(t);
        if (!lane) tot = t;
    }
    __syncthreads();
    return tot;
}

// ======== fp16 GEMM: C[M,N](f32) = A[M,K](f16) @ Bt[N,K](f16)^T (+ Res) ========
// BM=128, BN=128, BK=64 (4 x k16 steps); 8 warps of 32x64; 2 CTAs/SM.
// smem halves, row stride 72 (144 B) -> all fragment LDS conflict-free.
#define HSTR 72
#define HTILE (128*HSTR)                 // 9216 halves = 18432 B per buffer
#define SMEM_H (4*HTILE*2)               // 73728 B  (A0,A1,B0,B1)

__global__ void __launch_bounds__(256, 2)
gemm_h(const __half* __restrict__ A, int lda,
       const __half* __restrict__ Bt, int ldb,
       float* __restrict__ C, int ldc,
       const float* __restrict__ Res,
       int K, int npm, int npn, int roundOut,
       const int* __restrict__ pos, int doRope)
{
    extern __shared__ __half sh[];
    __half* sA = sh;                     // 2 buffers
    __half* sB = sh + 2*HTILE;

    // grouped rasterization for L2 reuse
    int pid = blockIdx.x;
    const int GROUP = 8;
    int npg = GROUP * npn;
    int gid = pid / npg;
    int firstm = gid * GROUP;
    int gsz = min(GROUP, npm - firstm);
    int pm = firstm + (pid % npg) % gsz;
    int pn = (pid % npg) / gsz;
    int m0 = pm * 128, n0 = pn * 128;

    int KT = K / 64;
    int tid = threadIdx.x;
    int wid = tid >> 5, lane = tid & 31;
    int wm = (wid & 3) * 32;
    int wn = (wid >> 2) * 64;
    int rl = lane >> 2, l3 = lane & 3;

    auto loadA = [&](int buf, int kt){
        __half* s = sA + buf * HTILE;
        int c = tid & 7;                   // 8 x 16B chunks per 128B row
        int r0 = tid >> 3;                 // 32 rows per pass
        const __half* gp = A + (long long)m0 * lda + kt * 64 + c * 8;
        #pragma unroll
        for (int w = 0; w < 4; w++){
            int row = r0 + 32 * w;
            cp16(smem_u32(s + row * HSTR + c * 8), gp + (long long)row * lda);
        }
    };
    auto loadB = [&](int buf, int kt){
        __half* s = sB + buf * HTILE;
        int c = tid & 7;
        int r0 = tid >> 3;
        const __half* gp = Bt + (long long)n0 * ldb + kt * 64 + c * 8;
        #pragma unroll
        for (int w = 0; w < 4; w++){
            int row = r0 + 32 * w;
            cp16(smem_u32(s + row * HSTR + c * 8), gp + (long long)row * ldb);
        }
    };

    float acc[2][8][4];
    #pragma unroll
    for (int i=0;i<2;i++)
        #pragma unroll
        for (int j=0;j<8;j++)
            #pragma unroll
            for (int r=0;r<4;r++) acc[i][j][r] = 0.f;

    loadA(0, 0); loadB(0, 0); CP_COMMIT();

    for (int kt = 0; kt < KT; kt++){
        int buf = kt & 1;
        if (kt + 1 < KT){
            loadA(buf ^ 1, kt + 1); loadB(buf ^ 1, kt + 1);
            CP_COMMIT();
            CP_WAIT(1);
        } else {
            CP_WAIT(0);
        }
        __syncthreads();
        const __half* sa = sA + buf * HTILE;
        const __half* sb = sB + buf * HTILE;

        #pragma unroll
        for (int ks = 0; ks < 4; ks++){
            int kk = ks * 16;
            unsigned a[2][4];
            #pragma unroll
            for (int mi = 0; mi < 2; mi++){
                const __half* ap = sa + (wm + mi * 16 + rl) * HSTR + kk + l3 * 2;
                a[mi][0] = *(const unsigned*)(ap);
                a[mi][1] = *(const unsigned*)(ap + 8 * HSTR);
                a[mi][2] = *(const unsigned*)(ap + 8);
                a[mi][3] = *(const unsigned*)(ap + 8 * HSTR + 8);
            }
            #pragma unroll
            for (int ni = 0; ni < 8; ni++){
                const __half* bp = sb + (wn + ni * 8 + rl) * HSTR + kk + l3 * 2;
                unsigned b0 = *(const unsigned*)(bp);
                unsigned b1 = *(const unsigned*)(bp + 8);
                #pragma unroll
                for (int mi = 0; mi < 2; mi++)
                    mma_h(acc[mi][ni], a[mi][0], a[mi][1], a[mi][2], a[mi][3], b0, b1);
            }
        }
        __syncthreads();
    }

    // epilogue (fp32 out; optional residual / rope / tf32-rounding)
    #pragma unroll
    for (int mi = 0; mi < 2; mi++){
        #pragma unroll
        for (int ni = 0; ni < 8; ni++){
            int row = m0 + wm + mi * 16 + rl;
            int col = n0 + wn + ni * 8 + l3 * 2;
            float v0 = acc[mi][ni][0];
            float v1 = acc[mi][ni][1];
            float v2 = acc[mi][ni][2];
            float v3 = acc[mi][ni][3];
            if (Res){
                float2 r01 = *(const float2*)(Res + (long long)row * ldc + col);
                float2 r23 = *(const float2*)(Res + (long long)(row + 8) * ldc + col);
                v0 += r01.x; v1 += r01.y; v2 += r23.x; v3 += r23.y;
            }
            if (doRope){
                int i = (col & 127) >> 1;
                float invf = g_invf[i];
                float a0 = (float)pos[row] * invf;
                float a1 = (float)pos[row + 8] * invf;
                float s0, c0, s1, c1;
                sincosf(a0, &s0, &c0);
                sincosf(a1, &s1, &c1);
                float t0 = v0 * c0 - v1 * s0;
                float t1 = v1 * c0 + v0 * s0;
                float t2 = v2 * c1 - v3 * s1;
                float t3 = v3 * c1 + v2 * s1;
                v0 = t0; v1 = t1; v2 = t2; v3 = t3;
            }
            if (roundOut | doRope){
                v0 = rna_tf32(v0); v1 = rna_tf32(v1);
                v2 = rna_tf32(v2); v3 = rna_tf32(v3);
            }
            *(float2*)(C + (long long)row * ldc + col)       = make_float2(v0, v1);
            *(float2*)(C + (long long)(row + 8) * ldc + col) = make_float2(v2, v3);
        }
    }
}

// ---------------- flash attention (tf32, proven; output cast to fp16) ----------
#define KSTR 140
#define VSTR 136
#define PSTR 76
#define KTILE 64
#define FLASH_SMEM ((2*KTILE*KSTR + 2*KTILE*VSTR + 8*16*PSTR)*4)   // 180224 B

__global__ void __launch_bounds__(256, 1)
flash_attn(const float* __restrict__ Q, const float* __restrict__ K,
           const float* __restrict__ V, __half* __restrict__ O,
           float alpha)
{
    extern __shared__ float sm[];
    float* sKb = sm;
    float* sVb = sm + 2*KTILE*KSTR;
    float* sP  = sVb + 2*KTILE*VSTR;

    int z = blockIdx.y;
    int b = z >> 4, h = z & 15;
    int qt = (gridDim.x - 1) - blockIdx.x;
    int q0 = qt * 128;
    const float* Qg = Q + ((long long)b * SEQ) * HIDDEN + h * HDIM;
    const float* Kg = K + ((long long)b * SEQ) * HIDDEN + h * HDIM;
    const float* Vg = V + ((long long)b * SEQ) * HIDDEN + h * HDIM;
    __half* Og = O + ((long long)b * SEQ) * HIDDEN + h * HDIM;

    int tid = threadIdx.x, wid = tid >> 5, lane = tid & 31;
    int rl = lane >> 2, l3 = lane & 3;
    int qr = q0 + wid * 16;
    float* sPw = sP + wid * 16 * PSTR;

    unsigned qf[16][4];
    #pragma unroll
    for (int ks = 0; ks < 16; ks++){
        const float* p0 = Qg + (long long)(qr + rl) * HIDDEN + ks * 8 + l3;
        const float* p1 = Qg + (long long)(qr + rl + 8) * HIDDEN + ks * 8 + l3;
        qf[ks][0] = __float_as_uint(p0[0]);
        qf[ks][1] = __float_as_uint(p1[0]);
        qf[ks][2] = __float_as_uint(p0[4]);
        qf[ks][3] = __float_as_uint(p1[4]);
    }

    float Oa[16][4];
    #pragma unroll
    for (int ni = 0; ni < 16; ni++){
        Oa[ni][0] = 0.f; Oa[ni][1] = 0.f; Oa[ni][2] = 0.f; Oa[ni][3] = 0.f;
    }
    float m0r = -1e30f, m1r = -1e30f, l0r = 0.f, l1r = 0.f;

    auto loadKV = [&](int buf, int t){
        int c = tid & 31, r0 = tid >> 5;
        const float* kp = Kg + (long long)(t * KTILE) * HIDDEN + c * 4;
        const float* vp = Vg + (long long)(t * KTILE) * HIDDEN + c * 4;
        float* dk = sKb + buf * KTILE * KSTR;
        float* dv = sVb + buf * KTILE * VSTR;
        #pragma unroll
        for (int w = 0; w < 8; w++){
            int row = r0 + 8 * w;
            cp16(smem_u32(dk + row * KSTR + c * 4), kp + (long long)row * HIDDEN);
        }
        #pragma unroll
        for (int w = 0; w < 8; w++){
            int row = r0 + 8 * w;
            cp16(smem_u32(dv + row * VSTR + c * 4), vp + (long long)row * HIDDEN);
        }
    };

    int nt = 2 * qt + 2;
    loadKV(0, 0); CP_COMMIT();

    for (int t = 0; t < nt; t++){
        int buf = t & 1;
        if (t + 1 < nt){
            loadKV(buf ^ 1, t + 1);
            CP_COMMIT();
            CP_WAIT(1);
        } else {
            CP_WAIT(0);
        }
        __syncthreads();
        const float* cK = sKb + buf * KTILE * KSTR;
        const float* cV = sVb + buf * KTILE * VSTR;
        int diag = (t >= 2 * qt);
        int k0 = t * KTILE;

        float Sa[8][4];
        #pragma unroll
        for (int ni = 0; ni < 8; ni++){
            Sa[ni][0]=0.f; Sa[ni][1]=0.f; Sa[ni][2]=0.f; Sa[ni][3]=0.f;
        }
        #pragma unroll
        for (int ks = 0; ks < 16; ks++){
            #pragma unroll
            for (int ni = 0; ni < 8; ni++){
                int n = ni * 8 + rl;
                unsigned b0 = __float_as_uint(cK[n * KSTR + ks * 8 + l3]);
                unsigned b1 = __float_as_uint(cK[n * KSTR + ks * 8 + 4 + l3]);
                mma_tf32(Sa[ni], qf[ks][0], qf[ks][1], qf[ks][2], qf[ks][3], b0, b1);
            }
        }

        int r0g = qr + rl, r1g = qr + rl + 8;
        float mx0 = -1e30f, mx1 = -1e30f;
        #pragma unroll
        for (int ni = 0; ni < 8; ni++){
            float x0 = Sa[ni][0] * alpha, x1 = Sa[ni][1] * alpha;
            float x2 = Sa[ni][2] * alpha, x3 = Sa[ni][3] * alpha;
            if (diag){
                int kg = k0 + ni * 8 + 2 * l3;
                if (kg     > r0g) x0 = -1e30f;
                if (kg + 1 > r0g) x1 = -1e30f;
                if (kg     > r1g) x2 = -1e30f;
                if (kg + 1 > r1g) x3 = -1e30f;
            }
            Sa[ni][0]=x0; Sa[ni][1]=x1; Sa[ni][2]=x2; Sa[ni][3]=x3;
            mx0 = fmaxf(mx0, fmaxf(x0, x1));
            mx1 = fmaxf(mx1, fmaxf(x2, x3));
        }
        mx0 = fmaxf(mx0, __shfl_xor_sync(0xffffffffu, mx0, 1));
        mx0 = fmaxf(mx0, __shfl_xor_sync(0xffffffffu, mx0, 2));
        mx1 = fmaxf(mx1, __shfl_xor_sync(0xffffffffu, mx1, 1));
        mx1 = fmaxf(mx1, __shfl_xor_sync(0xffffffffu, mx1, 2));

        float mn0 = fmaxf(m0r, mx0), mn1 = fmaxf(m1r, mx1);
        float cr0 = __expf(m0r - mn0), cr1 = __expf(m1r - mn1);
        m0r = mn0; m1r = mn1;
        l0r *= cr0; l1r *= cr1;
        #pragma unroll
        for (int ni = 0; ni < 16; ni++){
            Oa[ni][0] *= cr0; Oa[ni][1] *= cr0;
            Oa[ni][2] *= cr1; Oa[ni][3] *= cr1;
        }
        float rs0 = 0.f, rs1 = 0.f;
        #pragma unroll
        for (int ni = 0; ni < 8; ni++){
            float e0 = __expf(Sa[ni][0] - mn0);
            float e1 = __expf(Sa[ni][1] - mn0);
            float e2 = __expf(Sa[ni][2] - mn1);
            float e3 = __expf(Sa[ni][3] - mn1);
            rs0 += e0 + e1; rs1 += e2 + e3;
            int colp = ni * 8 + 2 * l3;
            *(float2*)(sPw + rl * PSTR + colp)       = make_float2(rna_tf32(e0), rna_tf32(e1));
            *(float2*)(sPw + (rl + 8) * PSTR + colp) = make_float2(rna_tf32(e2), rna_tf32(e3));
        }
        rs0 += __shfl_xor_sync(0xffffffffu, rs0, 1);
        rs0 += __shfl_xor_sync(0xffffffffu, rs0, 2);
        rs1 += __shfl_xor_sync(0xffffffffu, rs1, 1);
        rs1 += __shfl_xor_sync(0xffffffffu, rs1, 2);
        l0r += rs0; l1r += rs1;
        __syncwarp();

        #pragma unroll
        for (int ks = 0; ks < 8; ks++){
            unsigned a0 = __float_as_uint(sPw[rl * PSTR + ks * 8 + l3]);
            unsigned a1 = __float_as_uint(sPw[(rl + 8) * PSTR + ks * 8 + l3]);
            unsigned a2 = __float_as_uint(sPw[rl * PSTR + ks * 8 + 4 + l3]);
            unsigned a3 = __float_as_uint(sPw[(rl + 8) * PSTR + ks * 8 + 4 + l3]);
            #pragma unroll
            for (int ni = 0; ni < 16; ni++){
                unsigned b0 = __float_as_uint(cV[(ks * 8 + l3) * VSTR + ni * 8 + rl]);
                unsigned b1 = __float_as_uint(cV[(ks * 8 + 4 + l3) * VSTR + ni * 8 + rl]);
                mma_tf32(Oa[ni], a0, a1, a2, a3, b0, b1);
            }
        }
        __syncthreads();
    }

    // normalize + write fp16 (feeds WO gemm)
    float inv0 = 1.0f / l0r, inv1 = 1.0f / l1r;
    #pragma unroll
    for (int ni = 0; ni < 16; ni++){
        int col = ni * 8 + 2 * l3;
        *(__half2*)(Og + (long long)(qr + rl) * HIDDEN + col) =
            __floats2half2_rn(Oa[ni][0] * inv0, Oa[ni][1] * inv0);
        *(__half2*)(Og + (long long)(qr + rl + 8) * HIDDEN + col) =
            __floats2half2_rn(Oa[ni][2] * inv1, Oa[ni][3] * inv1);
    }
}

// ---------------- transpose + fp16-round: out[C,R] = h(in[R,C]^T) ------------
__global__ void transpose_h(const float* s0, __half* d0, const float* s1, __half* d1,
                            const float* s2, __half* d2, const float* s3, __half* d3,
                            int R, int C, int doInvf)
{
    __shared__ float t[32][33];
    const float* in; __half* out;
    switch (blockIdx.z){
        case 0:  in = s0; out = d0; break;
        case 1:  in = s1; out = d1; break;
        case 2:  in = s2; out = d2; break;
        default: in = s3; out = d3; break;
    }
    if (doInvf && blockIdx.x == 0 && blockIdx.y == 0 && blockIdx.z == 0){
        int f = threadIdx.y * 32 + threadIdx.x;
        if (f < 64) g_invf[f] = (float)exp(-(double)f * (log(500000.0) / 64.0));
    }
    int x  = blockIdx.x * 32 + threadIdx.x;
    int y0 = blockIdx.y * 32 + threadIdx.y;
    #pragma unroll
    for (int dy = 0; dy < 32; dy += 8)
        t[threadIdx.y + dy][threadIdx.x] = in[(long long)(y0 + dy) * C + x];
    __syncthreads();
    int ox  = blockIdx.y * 32 + threadIdx.x;
    int oy0 = blockIdx.x * 32 + threadIdx.y;
    #pragma unroll
    for (int dy = 0; dy < 32; dy += 8)
        out[(long long)(oy0 + dy) * R + ox] = __float2half_rn(t[threadIdx.x][threadIdx.y + dy]);
}

__global__ void rmsnorm_h(const float* __restrict__ X, const float* __restrict__ sc,
                          __half* __restrict__ O){
    long long base = (long long)blockIdx.x * HIDDEN;
    int tid = threadIdx.x;
    float v[8]; float ss = 0.f;
    #pragma unroll
    for (int i = 0; i < 8; i++){
        v[i] = X[base + tid + i * 256];
        ss += v[i] * v[i];
    }
    ss = blockReduceSum(ss);
    float r = rsqrtf(ss * (1.0f / (float)HIDDEN) + 1e-5f);
    #pragma unroll
    for (int i = 0; i < 8; i++){
        int c = tid + i * 256;
        O[base + c] = __float2half_rn(v[i] * r * sc[c]);
    }
}

__global__ void silu_mul_h(const float4* __restrict__ a, const float4* __restrict__ b,
                           __half* __restrict__ o, int n4){
    int i = blockIdx.x * blockDim.x + threadIdx.x;
    int st = gridDim.x * blockDim.x;
    for (; i < n4; i += st){
        float4 x = a[i], y = b[i];
        float s0 = x.x / (1.0f + expf(-x.x));
        float s1 = x.y / (1.0f + expf(-x.y));
        float s2 = x.z / (1.0f + expf(-x.z));
        float s3 = x.w / (1.0f + expf(-x.w));
        __half2 h01 = __floats2half2_rn(s0 * y.x, s1 * y.y);
        __half2 h23 = __floats2half2_rn(s2 * y.z, s3 * y.w);
        *(__half2*)(o + (size_t)i * 4)     = h01;
        *(__half2*)(o + (size_t)i * 4 + 2) = h23;
    }
}

// ---------------- launch ----------------
extern "C" void kernel_launch(void* const* d_in, const int* in_sizes, int n_in,
                              void* d_out, int out_size)
{
    const float* x   = (const float*)d_in[0];
    const int*   pos = (const int*)d_in[1];
    // d_in[2] = mask (causal; handled analytically)
    const float* wq  = (const float*)d_in[3];
    const float* wk  = (const float*)d_in[4];
    const float* wv  = (const float*)d_in[5];
    const float* wo  = (const float*)d_in[6];
    const float* asc = (const float*)d_in[7];
    const float* fsc = (const float*)d_in[8];
    const float* w1  = (const float*)d_in[9];
    const float* w3  = (const float*)d_in[10];
    const float* w2  = (const float*)d_in[11];
    float* out = (float*)d_out;

    __half *p_xnh,*p_aoh,*p_ffnh,*p_g1h;
    float *p_q,*p_k,*p_v,*p_h,*p_g1,*p_g3;
    __half *p_wq,*p_wk,*p_wv,*p_wo,*p_w1,*p_w3,*p_w2;
    cudaGetSymbolAddress((void**)&p_xnh, g_xnh);
    cudaGetSymbolAddress((void**)&p_q,   g_q);
    cudaGetSymbolAddress((void**)&p_k,   g_k);
    cudaGetSymbolAddress((void**)&p_v,   g_v);
    cudaGetSymbolAddress((void**)&p_aoh, g_aoh);
    cudaGetSymbolAddress((void**)&p_h,   g_h);
    cudaGetSymbolAddress((void**)&p_ffnh,g_ffnh);
    cudaGetSymbolAddress((void**)&p_g1,  g_g1);
    cudaGetSymbolAddress((void**)&p_g3,  g_g3);
    cudaGetSymbolAddress((void**)&p_g1h, g_g1h);
    cudaGetSymbolAddress((void**)&p_wq,  g_wq);
    cudaGetSymbolAddress((void**)&p_wk,  g_wk);
    cudaGetSymbolAddress((void**)&p_wv,  g_wv);
    cudaGetSymbolAddress((void**)&p_wo,  g_wo);
    cudaGetSymbolAddress((void**)&p_w1,  g_w1);
    cudaGetSymbolAddress((void**)&p_w3,  g_w3);
    cudaGetSymbolAddress((void**)&p_w2,  g_w2);

    cudaFuncSetAttribute(gemm_h, cudaFuncAttributeMaxDynamicSharedMemorySize, SMEM_H);
    cudaFuncSetAttribute(flash_attn, cudaFuncAttributeMaxDynamicSharedMemorySize, FLASH_SMEM);

    // 0a. transpose+fp16 attn weights [2048,2048] -> [N,K]; init invf table
    transpose_h<<<dim3(64,64,4), dim3(32,8)>>>(wq,p_wq, wk,p_wk, wv,p_wv, wo,p_wo,
                                               HIDDEN, HIDDEN, 1);
    // 0b. w1,w3 [2048,5632] -> [5632,2048]
    transpose_h<<<dim3(176,64,2), dim3(32,8)>>>(w1,p_w1, w3,p_w3, nullptr,nullptr,
                                                nullptr,nullptr, HIDDEN, FFDIM, 0);
    // 0c. w2 [5632,2048] -> [2048,5632]
    transpose_h<<<dim3(64,176,1), dim3(32,8)>>>(w2,p_w2, nullptr,nullptr, nullptr,nullptr,
                                                nullptr,nullptr, FFDIM, HIDDEN, 0);

    // 1. rmsnorm (attn) -> fp16
    rmsnorm_h<<<NTOK,256>>>(x, asc, p_xnh);

    // 2-4. Q/K/V projections (rope fused into Q,K epilogues). launch idx 5 = K (profiled)
    dim3 gProj(32*16, 1, 1);
    gemm_h<<<gProj,256,SMEM_H>>>(p_xnh,HIDDEN, p_wq,HIDDEN, p_q,HIDDEN,
                                 nullptr, HIDDEN, 32,16, 0, pos, 1);
    gemm_h<<<gProj,256,SMEM_H>>>(p_xnh,HIDDEN, p_wk,HIDDEN, p_k,HIDDEN,
                                 nullptr, HIDDEN, 32,16, 0, pos, 1);
    gemm_h<<<gProj,256,SMEM_H>>>(p_xnh,HIDDEN, p_wv,HIDDEN, p_v,HIDDEN,
                                 nullptr, HIDDEN, 32,16, 1, nullptr, 0);

    // 5. flash attention (tf32; writes fp16 attnout)
    flash_attn<<<dim3(16, BATCHN*NHEADS),256,FLASH_SMEM>>>(
        p_q, p_k, p_v, p_aoh, 0.08838834764831845f);

    // 6. h = x + attn_out @ wo
    gemm_h<<<gProj,256,SMEM_H>>>(p_aoh,HIDDEN, p_wo,HIDDEN, p_h,HIDDEN,
                                 x, HIDDEN, 32,16, 0, nullptr, 0);

    // 7. rmsnorm (ffn) -> fp16
    rmsnorm_h<<<NTOK,256>>>(p_h, fsc, p_ffnh);

    // 8-9. g1 = ff @ w1 ; g3 = ff @ w3  (N=5632 = 44 tiles)
    dim3 gFF(32*44, 1, 1);
    gemm_h<<<gFF,256,SMEM_H>>>(p_ffnh,HIDDEN, p_w1,HIDDEN, p_g1,FFDIM,
                               nullptr, HIDDEN, 32,44, 0, nullptr, 0);
    gemm_h<<<gFF,256,SMEM_H>>>(p_ffnh,HIDDEN, p_w3,HIDDEN, p_g3,FFDIM,
                               nullptr, HIDDEN, 32,44, 0, nullptr, 0);

    // 10. g1h = fp16(silu(g1) * g3)
    silu_mul_h<<<4096,256>>>((const float4*)p_g1, (const float4*)p_g3, p_g1h,
                             (int)((size_t)NTOK*FFDIM/4));

    // 11. out = h + g1h @ w2   (K = 5632)
    gemm_h<<<gProj,256,SMEM_H>>>(p_g1h,FFDIM, p_w2,FFDIM, out,HIDDEN,
                                 p_h, FFDIM, 32,16, 0, nullptr, 0);
}

// round 9
// speedup vs baseline: 1.7352x; 1.6303x over previous
#include <cuda_runtime.h>
#include <cuda_fp16.h>
#include <cstdint>
#include <math.h>

#define HIDDEN 2048
#define NHEADS 16
#define HDIM 128
#define FFDIM 5632
#define BATCHN 2
#define SEQ 2048
#define NTOK (BATCHN*SEQ)   // 4096

// ---------------- scratch ----------------
__device__ __half g_xnh[NTOK*HIDDEN];
__device__ float  g_q[NTOK*HIDDEN];
__device__ float  g_k[NTOK*HIDDEN];
__device__ float  g_v[NTOK*HIDDEN];
__device__ __half g_aoh[NTOK*HIDDEN];
__device__ float  g_h[NTOK*HIDDEN];
__device__ __half g_ffnh[NTOK*HIDDEN];
__device__ __half g_g1h[(size_t)NTOK*FFDIM];
__device__ float  g_invf[64];
// fp16 TRANSPOSED weights [N, K] K-major
__device__ __half g_wq[HIDDEN*HIDDEN];
__device__ __half g_wk[HIDDEN*HIDDEN];
__device__ __half g_wv[HIDDEN*HIDDEN];
__device__ __half g_wo[HIDDEN*HIDDEN];
__device__ __half g_w1[(size_t)HIDDEN*FFDIM];
__device__ __half g_w3[(size_t)HIDDEN*FFDIM];
__device__ __half g_w2[(size_t)FFDIM*HIDDEN];

// ---------------- helpers ----------------
__device__ __forceinline__ float rna_tf32(float x){
    unsigned r; asm("cvt.rna.tf32.f32 %0, %1;" : "=r"(r) : "f"(x));
    return __uint_as_float(r);
}
__device__ __forceinline__ unsigned smem_u32(const void* p){
    return (unsigned)__cvta_generic_to_shared(p);
}
__device__ __forceinline__ void cp16(unsigned s, const void* g){
    asm volatile("cp.async.cg.shared.global [%0], [%1], 16;\n" :: "r"(s), "l"(g));
}
#define CP_COMMIT() asm volatile("cp.async.commit_group;\n")
#define CP_WAIT(n)  asm volatile("cp.async.wait_group %0;\n" :: "n"(n))

__device__ __forceinline__ void mma_tf32(float c[4],
        unsigned a0, unsigned a1, unsigned a2, unsigned a3,
        unsigned b0, unsigned b1){
    asm volatile("mma.sync.aligned.m16n8k8.row.col.f32.tf32.tf32.f32 "
        "{%0,%1,%2,%3},{%4,%5,%6,%7},{%8,%9},{%0,%1,%2,%3};\n"
        : "+f"(c[0]), "+f"(c[1]), "+f"(c[2]), "+f"(c[3])
        : "r"(a0), "r"(a1), "r"(a2), "r"(a3), "r"(b0), "r"(b1));
}
__device__ __forceinline__ void mma_h(float c[4],
        unsigned a0, unsigned a1, unsigned a2, unsigned a3,
        unsigned b0, unsigned b1){
    asm volatile("mma.sync.aligned.m16n8k16.row.col.f32.f16.f16.f32 "
        "{%0,%1,%2,%3},{%4,%5,%6,%7},{%8,%9},{%0,%1,%2,%3};\n"
        : "+f"(c[0]), "+f"(c[1]), "+f"(c[2]), "+f"(c[3])
        : "r"(a0), "r"(a1), "r"(a2), "r"(a3), "r"(b0), "r"(b1));
}

__device__ __forceinline__ float warpReduceSum(float v){
    #pragma unroll
    for (int o=16;o;o>>=1) v += __shfl_xor_sync(0xffffffffu, v, o);
    return v;
}
__device__ float blockReduceSum(float v){   // 256 threads
    __shared__ float s[8]; __shared__ float tot;
    int lane = threadIdx.x & 31, w = threadIdx.x >> 5;
    v = warpReduceSum(v);
    if (!lane) s[w] = v;
    __syncthreads();
    if (w == 0){
        float t = (lane < 8) ? s[lane] : 0.f;
        t = warpReduceSum(t);
        if (!lane) tot = t;
    }
    __syncthreads();
    return tot;
}

// ======== fp16 GEMM v2: 3-stage pipeline, 1 barrier/iter ========
// C[M,N](f32) = A[M,K](f16) @ Bt[N,K](f16)^T (+ Res). BM=BN=128, BK=64.
// 8 warps of 32x64; 2 CTAs/SM; smem 3 stages x (A 18KB + B 18KB) = 108KB.
#define HSTR 72
#define HTILE (128*HSTR)                 // halves per (A or B) stage buffer
#define SMEM_H (3*2*HTILE*2)             // 110592 B

__global__ void __launch_bounds__(256, 2)
gemm_h(const __half* __restrict__ A, int lda,
       const __half* __restrict__ Bt, int ldb,
       float* __restrict__ C, int ldc,
       const float* __restrict__ Res,
       int K, int npm, int npn, int roundOut,
       const int* __restrict__ pos, int doRope)
{
    extern __shared__ __half sh[];

    int pid = blockIdx.x;
    const int GROUP = 16;
    int npg = GROUP * npn;
    int gid = pid / npg;
    int firstm = gid * GROUP;
    int gsz = min(GROUP, npm - firstm);
    int pm = firstm + (pid % npg) % gsz;
    int pn = (pid % npg) / gsz;
    int m0 = pm * 128, n0 = pn * 128;

    int KT = K / 64;
    int tid = threadIdx.x;
    int wid = tid >> 5, lane = tid & 31;
    int wm = (wid & 3) * 32;
    int wn = (wid >> 2) * 64;
    int rl = lane >> 2, l3 = lane & 3;

    auto loadAB = [&](int st, int kt){
        __half* sa = sh + st * (2*HTILE);
        __half* sb = sa + HTILE;
        int c = tid & 7;
        int r0 = tid >> 3;
        const __half* ga = A  + (long long)m0 * lda + kt * 64 + c * 8;
        const __half* gb = Bt + (long long)n0 * ldb + kt * 64 + c * 8;
        #pragma unroll
        for (int w = 0; w < 4; w++){
            int row = r0 + 32 * w;
            cp16(smem_u32(sa + row * HSTR + c * 8), ga + (long long)row * lda);
        }
        #pragma unroll
        for (int w = 0; w < 4; w++){
            int row = r0 + 32 * w;
            cp16(smem_u32(sb + row * HSTR + c * 8), gb + (long long)row * ldb);
        }
    };

    float acc[2][8][4];
    #pragma unroll
    for (int i=0;i<2;i++)
        #pragma unroll
        for (int j=0;j<8;j++)
            #pragma unroll
            for (int r=0;r<4;r++) acc[i][j][r] = 0.f;

    loadAB(0, 0); CP_COMMIT();
    if (KT > 1) loadAB(1, 1);
    CP_COMMIT();

    for (int kt = 0; kt < KT; kt++){
        int cur = kt % 3;
        CP_WAIT(1);
        __syncthreads();
        if (kt + 2 < KT) loadAB((kt + 2) % 3, kt + 2);
        CP_COMMIT();

        const __half* sa = sh + cur * (2*HTILE);
        const __half* sb = sa + HTILE;
        #pragma unroll
        for (int ks = 0; ks < 4; ks++){
            int kk = ks * 16;
            unsigned a[2][4];
            #pragma unroll
            for (int mi = 0; mi < 2; mi++){
                const __half* ap = sa + (wm + mi * 16 + rl) * HSTR + kk + l3 * 2;
                a[mi][0] = *(const unsigned*)(ap);
                a[mi][1] = *(const unsigned*)(ap + 8 * HSTR);
                a[mi][2] = *(const unsigned*)(ap + 8);
                a[mi][3] = *(const unsigned*)(ap + 8 * HSTR + 8);
            }
            #pragma unroll
            for (int ni = 0; ni < 8; ni++){
                const __half* bp = sb + (wn + ni * 8 + rl) * HSTR + kk + l3 * 2;
                unsigned b0 = *(const unsigned*)(bp);
                unsigned b1 = *(const unsigned*)(bp + 8);
                #pragma unroll
                for (int mi = 0; mi < 2; mi++)
                    mma_h(acc[mi][ni], a[mi][0], a[mi][1], a[mi][2], a[mi][3], b0, b1);
            }
        }
    }

    // epilogue
    #pragma unroll
    for (int mi = 0; mi < 2; mi++){
        #pragma unroll
        for (int ni = 0; ni < 8; ni++){
            int row = m0 + wm + mi * 16 + rl;
            int col = n0 + wn + ni * 8 + l3 * 2;
            float v0 = acc[mi][ni][0];
            float v1 = acc[mi][ni][1];
            float v2 = acc[mi][ni][2];
            float v3 = acc[mi][ni][3];
            if (Res){
                float2 r01 = *(const float2*)(Res + (long long)row * ldc + col);
                float2 r23 = *(const float2*)(Res + (long long)(row + 8) * ldc + col);
                v0 += r01.x; v1 += r01.y; v2 += r23.x; v3 += r23.y;
            }
            if (doRope){
                int i = (col & 127) >> 1;
                float invf = g_invf[i];
                float a0 = (float)pos[row] * invf;
                float a1 = (float)pos[row + 8] * invf;
                float s0, c0, s1, c1;
                sincosf(a0, &s0, &c0);
                sincosf(a1, &s1, &c1);
                float t0 = v0 * c0 - v1 * s0;
                float t1 = v1 * c0 + v0 * s0;
                float t2 = v2 * c1 - v3 * s1;
                float t3 = v3 * c1 + v2 * s1;
                v0 = t0; v1 = t1; v2 = t2; v3 = t3;
            }
            if (roundOut | doRope){
                v0 = rna_tf32(v0); v1 = rna_tf32(v1);
                v2 = rna_tf32(v2); v3 = rna_tf32(v3);
            }
            *(float2*)(C + (long long)row * ldc + col)       = make_float2(v0, v1);
            *(float2*)(C + (long long)(row + 8) * ldc + col) = make_float2(v2, v3);
        }
    }
}

// ======== fused FFN: g1h = fp16( silu(A@W1^T) * (A@W3^T) ) ========
// BM=128, BN=64, BK=64; 8 warps of 32x32 (x2 accumulators); 3-stage pipeline.
// smem/stage: A 18KB + B1 9KB + B3 9KB = 36KB; 3 stages = 108KB; 2 CTAs/SM.
#define FBTILE (64*HSTR)
#define FSTAGE (HTILE + 2*FBTILE)
#define SMEM_F (3*FSTAGE*2)              // 110592 B

__global__ void __launch_bounds__(256, 2)
gemm_ff(const __half* __restrict__ A, int lda,
        const __half* __restrict__ B1t, const __half* __restrict__ B3t, int ldb,
        __half* __restrict__ O, int ldo,
        int K, int npm, int npn)
{
    extern __shared__ __half sh[];

    int pid = blockIdx.x;
    const int GROUP = 16;
    int npg = GROUP * npn;
    int gid = pid / npg;
    int firstm = gid * GROUP;
    int gsz = min(GROUP, npm - firstm);
    int pm = firstm + (pid % npg) % gsz;
    int pn = (pid % npg) / gsz;
    int m0 = pm * 128, n0 = pn * 64;

    int KT = K / 64;
    int tid = threadIdx.x;
    int wid = tid >> 5, lane = tid & 31;
    int wm = (wid & 3) * 32;
    int wn = (wid >> 2) * 32;
    int rl = lane >> 2, l3 = lane & 3;

    auto loadAB = [&](int st, int kt){
        __half* sa = sh + st * FSTAGE;
        __half* sb1 = sa + HTILE;
        __half* sb3 = sb1 + FBTILE;
        int c = tid & 7;
        int r0 = tid >> 3;
        const __half* ga = A + (long long)m0 * lda + kt * 64 + c * 8;
        #pragma unroll
        for (int w = 0; w < 4; w++){
            int row = r0 + 32 * w;
            cp16(smem_u32(sa + row * HSTR + c * 8), ga + (long long)row * lda);
        }
        const __half* g1 = B1t + (long long)n0 * ldb + kt * 64 + c * 8;
        const __half* g3 = B3t + (long long)n0 * ldb + kt * 64 + c * 8;
        #pragma unroll
        for (int w = 0; w < 2; w++){
            int row = r0 + 32 * w;
            cp16(smem_u32(sb1 + row * HSTR + c * 8), g1 + (long long)row * ldb);
        }
        #pragma unroll
        for (int w = 0; w < 2; w++){
            int row = r0 + 32 * w;
            cp16(smem_u32(sb3 + row * HSTR + c * 8), g3 + (long long)row * ldb);
        }
    };

    float ac1[2][4][4], ac3[2][4][4];
    #pragma unroll
    for (int i=0;i<2;i++)
        #pragma unroll
        for (int j=0;j<4;j++)
            #pragma unroll
            for (int r=0;r<4;r++){ ac1[i][j][r] = 0.f; ac3[i][j][r] = 0.f; }

    loadAB(0, 0); CP_COMMIT();
    if (KT > 1) loadAB(1, 1);
    CP_COMMIT();

    for (int kt = 0; kt < KT; kt++){
        int cur = kt % 3;
        CP_WAIT(1);
        __syncthreads();
        if (kt + 2 < KT) loadAB((kt + 2) % 3, kt + 2);
        CP_COMMIT();

        const __half* sa  = sh + cur * FSTAGE;
        const __half* sb1 = sa + HTILE;
        const __half* sb3 = sb1 + FBTILE;
        #pragma unroll
        for (int ks = 0; ks < 4; ks++){
            int kk = ks * 16;
            unsigned a[2][4];
            #pragma unroll
            for (int mi = 0; mi < 2; mi++){
                const __half* ap = sa + (wm + mi * 16 + rl) * HSTR + kk + l3 * 2;
                a[mi][0] = *(const unsigned*)(ap);
                a[mi][1] = *(const unsigned*)(ap + 8 * HSTR);
                a[mi][2] = *(const unsigned*)(ap + 8);
                a[mi][3] = *(const unsigned*)(ap + 8 * HSTR + 8);
            }
            #pragma unroll
            for (int ni = 0; ni < 4; ni++){
                const __half* b1p = sb1 + (wn + ni * 8 + rl) * HSTR + kk + l3 * 2;
                const __half* b3p = sb3 + (wn + ni * 8 + rl) * HSTR + kk + l3 * 2;
                unsigned b10 = *(const unsigned*)(b1p);
                unsigned b11 = *(const unsigned*)(b1p + 8);
                unsigned b30 = *(const unsigned*)(b3p);
                unsigned b31 = *(const unsigned*)(b3p + 8);
                #pragma unroll
                for (int mi = 0; mi < 2; mi++){
                    mma_h(ac1[mi][ni], a[mi][0], a[mi][1], a[mi][2], a[mi][3], b10, b11);
                    mma_h(ac3[mi][ni], a[mi][0], a[mi][1], a[mi][2], a[mi][3], b30, b31);
                }
            }
        }
    }

    // epilogue: silu(g1)*g3 -> fp16
    #pragma unroll
    for (int mi = 0; mi < 2; mi++){
        #pragma unroll
        for (int ni = 0; ni < 4; ni++){
            int row = m0 + wm + mi * 16 + rl;
            int col = n0 + wn + ni * 8 + l3 * 2;
            float x0 = ac1[mi][ni][0], x1 = ac1[mi][ni][1];
            float x2 = ac1[mi][ni][2], x3 = ac1[mi][ni][3];
            float y0 = ac3[mi][ni][0], y1 = ac3[mi][ni][1];
            float y2 = ac3[mi][ni][2], y3 = ac3[mi][ni][3];
            float s0 = x0 / (1.0f + __expf(-x0)) * y0;
            float s1 = x1 / (1.0f + __expf(-x1)) * y1;
            float s2 = x2 / (1.0f + __expf(-x2)) * y2;
            float s3 = x3 / (1.0f + __expf(-x3)) * y3;
            *(__half2*)(O + (long long)row * ldo + col)       = __floats2half2_rn(s0, s1);
            *(__half2*)(O + (long long)(row + 8) * ldo + col) = __floats2half2_rn(s2, s3);
        }
    }
}

// ---------------- flash attention (tf32, proven; fp16 out) ----------------
#define KSTR 140
#define VSTR 136
#define PSTR 76
#define KTILE 64
#define FLASH_SMEM ((2*KTILE*KSTR + 2*KTILE*VSTR + 8*16*PSTR)*4)   // 180224 B

__global__ void __launch_bounds__(256, 1)
flash_attn(const float* __restrict__ Q, const float* __restrict__ K,
           const float* __restrict__ V, __half* __restrict__ O,
           float alpha)
{
    extern __shared__ float sm[];
    float* sKb = sm;
    float* sVb = sm + 2*KTILE*KSTR;
    float* sP  = sVb + 2*KTILE*VSTR;

    int z = blockIdx.y;
    int b = z >> 4, h = z & 15;
    int qt = (gridDim.x - 1) - blockIdx.x;
    int q0 = qt * 128;
    const float* Qg = Q + ((long long)b * SEQ) * HIDDEN + h * HDIM;
    const float* Kg = K + ((long long)b * SEQ) * HIDDEN + h * HDIM;
    const float* Vg = V + ((long long)b * SEQ) * HIDDEN + h * HDIM;
    __half* Og = O + ((long long)b * SEQ) * HIDDEN + h * HDIM;

    int tid = threadIdx.x, wid = tid >> 5, lane = tid & 31;
    int rl = lane >> 2, l3 = lane & 3;
    int qr = q0 + wid * 16;
    float* sPw = sP + wid * 16 * PSTR;

    unsigned qf[16][4];
    #pragma unroll
    for (int ks = 0; ks < 16; ks++){
        const float* p0 = Qg + (long long)(qr + rl) * HIDDEN + ks * 8 + l3;
        const float* p1 = Qg + (long long)(qr + rl + 8) * HIDDEN + ks * 8 + l3;
        qf[ks][0] = __float_as_uint(p0[0]);
        qf[ks][1] = __float_as_uint(p1[0]);
        qf[ks][2] = __float_as_uint(p0[4]);
        qf[ks][3] = __float_as_uint(p1[4]);
    }

    float Oa[16][4];
    #pragma unroll
    for (int ni = 0; ni < 16; ni++){
        Oa[ni][0] = 0.f; Oa[ni][1] = 0.f; Oa[ni][2] = 0.f; Oa[ni][3] = 0.f;
    }
    float m0r = -1e30f, m1r = -1e30f, l0r = 0.f, l1r = 0.f;

    auto loadKV = [&](int buf, int t){
        int c = tid & 31, r0 = tid >> 5;
        const float* kp = Kg + (long long)(t * KTILE) * HIDDEN + c * 4;
        const float* vp = Vg + (long long)(t * KTILE) * HIDDEN + c * 4;
        float* dk = sKb + buf * KTILE * KSTR;
        float* dv = sVb + buf * KTILE * VSTR;
        #pragma unroll
        for (int w = 0; w < 8; w++){
            int row = r0 + 8 * w;
            cp16(smem_u32(dk + row * KSTR + c * 4), kp + (long long)row * HIDDEN);
        }
        #pragma unroll
        for (int w = 0; w < 8; w++){
            int row = r0 + 8 * w;
            cp16(smem_u32(dv + row * VSTR + c * 4), vp + (long long)row * HIDDEN);
        }
    };

    int nt = 2 * qt + 2;
    loadKV(0, 0); CP_COMMIT();

    for (int t = 0; t < nt; t++){
        int buf = t & 1;
        if (t + 1 < nt){
            loadKV(buf ^ 1, t + 1);
            CP_COMMIT();
            CP_WAIT(1);
        } else {
            CP_WAIT(0);
        }
        __syncthreads();
        const float* cK = sKb + buf * KTILE * KSTR;
        const float* cV = sVb + buf * KTILE * VSTR;
        int diag = (t >= 2 * qt);
        int k0 = t * KTILE;

        float Sa[8][4];
        #pragma unroll
        for (int ni = 0; ni < 8; ni++){
            Sa[ni][0]=0.f; Sa[ni][1]=0.f; Sa[ni][2]=0.f; Sa[ni][3]=0.f;
        }
        #pragma unroll
        for (int ks = 0; ks < 16; ks++){
            #pragma unroll
            for (int ni = 0; ni < 8; ni++){
                int n = ni * 8 + rl;
                unsigned b0 = __float_as_uint(cK[n * KSTR + ks * 8 + l3]);
                unsigned b1 = __float_as_uint(cK[n * KSTR + ks * 8 + 4 + l3]);
                mma_tf32(Sa[ni], qf[ks][0], qf[ks][1], qf[ks][2], qf[ks][3], b0, b1);
            }
        }

        int r0g = qr + rl, r1g = qr + rl + 8;
        float mx0 = -1e30f, mx1 = -1e30f;
        #pragma unroll
        for (int ni = 0; ni < 8; ni++){
            float x0 = Sa[ni][0] * alpha, x1 = Sa[ni][1] * alpha;
            float x2 = Sa[ni][2] * alpha, x3 = Sa[ni][3] * alpha;
            if (diag){
                int kg = k0 + ni * 8 + 2 * l3;
                if (kg     > r0g) x0 = -1e30f;
                if (kg + 1 > r0g) x1 = -1e30f;
                if (kg     > r1g) x2 = -1e30f;
                if (kg + 1 > r1g) x3 = -1e30f;
            }
            Sa[ni][0]=x0; Sa[ni][1]=x1; Sa[ni][2]=x2; Sa[ni][3]=x3;
            mx0 = fmaxf(mx0, fmaxf(x0, x1));
            mx1 = fmaxf(mx1, fmaxf(x2, x3));
        }
        mx0 = fmaxf(mx0, __shfl_xor_sync(0xffffffffu, mx0, 1));
        mx0 = fmaxf(mx0, __shfl_xor_sync(0xffffffffu, mx0, 2));
        mx1 = fmaxf(mx1, __shfl_xor_sync(0xffffffffu, mx1, 1));
        mx1 = fmaxf(mx1, __shfl_xor_sync(0xffffffffu, mx1, 2));

        float mn0 = fmaxf(m0r, mx0), mn1 = fmaxf(m1r, mx1);
        float cr0 = __expf(m0r - mn0), cr1 = __expf(m1r - mn1);
        m0r = mn0; m1r = mn1;
        l0r *= cr0; l1r *= cr1;
        #pragma unroll
        for (int ni = 0; ni < 16; ni++){
            Oa[ni][0] *= cr0; Oa[ni][1] *= cr0;
            Oa[ni][2] *= cr1; Oa[ni][3] *= cr1;
        }
        float rs0 = 0.f, rs1 = 0.f;
        #pragma unroll
        for (int ni = 0; ni < 8; ni++){
            float e0 = __expf(Sa[ni][0] - mn0);
            float e1 = __expf(Sa[ni][1] - mn0);
            float e2 = __expf(Sa[ni][2] - mn1);
            float e3 = __expf(Sa[ni][3] - mn1);
            rs0 += e0 + e1; rs1 += e2 + e3;
            int colp = ni * 8 + 2 * l3;
            *(float2*)(sPw + rl * PSTR + colp)       = make_float2(rna_tf32(e0), rna_tf32(e1));
            *(float2*)(sPw + (rl + 8) * PSTR + colp) = make_float2(rna_tf32(e2), rna_tf32(e3));
        }
        rs0 += __shfl_xor_sync(0xffffffffu, rs0, 1);
        rs0 += __shfl_xor_sync(0xffffffffu, rs0, 2);
        rs1 += __shfl_xor_sync(0xffffffffu, rs1, 1);
        rs1 += __shfl_xor_sync(0xffffffffu, rs1, 2);
        l0r += rs0; l1r += rs1;
        __syncwarp();

        #pragma unroll
        for (int ks = 0; ks < 8; ks++){
            unsigned a0 = __float_as_uint(sPw[rl * PSTR + ks * 8 + l3]);
            unsigned a1 = __float_as_uint(sPw[(rl + 8) * PSTR + ks * 8 + l3]);
            unsigned a2 = __float_as_uint(sPw[rl * PSTR + ks * 8 + 4 + l3]);
            unsigned a3 = __float_as_uint(sPw[(rl + 8) * PSTR + ks * 8 + 4 + l3]);
            #pragma unroll
            for (int ni = 0; ni < 16; ni++){
                unsigned b0 = __float_as_uint(cV[(ks * 8 + l3) * VSTR + ni * 8 + rl]);
                unsigned b1 = __float_as_uint(cV[(ks * 8 + 4 + l3) * VSTR + ni * 8 + rl]);
                mma_tf32(Oa[ni], a0, a1, a2, a3, b0, b1);
            }
        }
        __syncthreads();
    }

    float inv0 = 1.0f / l0r, inv1 = 1.0f / l1r;
    #pragma unroll
    for (int ni = 0; ni < 16; ni++){
        int col = ni * 8 + 2 * l3;
        *(__half2*)(Og + (long long)(qr + rl) * HIDDEN + col) =
            __floats2half2_rn(Oa[ni][0] * inv0, Oa[ni][1] * inv0);
        *(__half2*)(Og + (long long)(qr + rl + 8) * HIDDEN + col) =
            __floats2half2_rn(Oa[ni][2] * inv1, Oa[ni][3] * inv1);
    }
}

// ---------------- transpose + fp16: out[C,R] = h(in[R,C]^T) ------------
__global__ void transpose_h(const float* s0, __half* d0, const float* s1, __half* d1,
                            const float* s2, __half* d2, const float* s3, __half* d3,
                            int R, int C, int doInvf)
{
    __shared__ float t[32][33];
    const float* in; __half* out;
    switch (blockIdx.z){
        case 0:  in = s0; out = d0; break;
        case 1:  in = s1; out = d1; break;
        case 2:  in = s2; out = d2; break;
        default: in = s3; out = d3; break;
    }
    if (doInvf && blockIdx.x == 0 && blockIdx.y == 0 && blockIdx.z == 0){
        int f = threadIdx.y * 32 + threadIdx.x;
        if (f < 64) g_invf[f] = (float)exp(-(double)f * (log(500000.0) / 64.0));
    }
    int x  = blockIdx.x * 32 + threadIdx.x;
    int y0 = blockIdx.y * 32 + threadIdx.y;
    #pragma unroll
    for (int dy = 0; dy < 32; dy += 8)
        t[threadIdx.y + dy][threadIdx.x] = in[(long long)(y0 + dy) * C + x];
    __syncthreads();
    int ox  = blockIdx.y * 32 + threadIdx.x;
    int oy0 = blockIdx.x * 32 + threadIdx.y;
    #pragma unroll
    for (int dy = 0; dy < 32; dy += 8)
        out[(long long)(oy0 + dy) * R + ox] = __float2half_rn(t[threadIdx.x][threadIdx.y + dy]);
}

__global__ void rmsnorm_h(const float* __restrict__ X, const float* __restrict__ sc,
                          __half* __restrict__ O){
    long long base = (long long)blockIdx.x * HIDDEN;
    int tid = threadIdx.x;
    float v[8]; float ss = 0.f;
    #pragma unroll
    for (int i = 0; i < 8; i++){
        v[i] = X[base + tid + i * 256];
        ss += v[i] * v[i];
    }
    ss = blockReduceSum(ss);
    float r = rsqrtf(ss * (1.0f / (float)HIDDEN) + 1e-5f);
    #pragma unroll
    for (int i = 0; i < 8; i++){
        int c = tid + i * 256;
        O[base + c] = __float2half_rn(v[i] * r * sc[c]);
    }
}

// ---------------- launch ----------------
extern "C" void kernel_launch(void* const* d_in, const int* in_sizes, int n_in,
                              void* d_out, int out_size)
{
    const float* x   = (const float*)d_in[0];
    const int*   pos = (const int*)d_in[1];
    // d_in[2] = mask (causal; handled analytically)
    const float* wq  = (const float*)d_in[3];
    const float* wk  = (const float*)d_in[4];
    const float* wv  = (const float*)d_in[5];
    const float* wo  = (const float*)d_in[6];
    const float* asc = (const float*)d_in[7];
    const float* fsc = (const float*)d_in[8];
    const float* w1  = (const float*)d_in[9];
    const float* w3  = (const float*)d_in[10];
    const float* w2  = (const float*)d_in[11];
    float* out = (float*)d_out;

    __half *p_xnh,*p_aoh,*p_ffnh,*p_g1h;
    float *p_q,*p_k,*p_v,*p_h;
    __half *p_wq,*p_wk,*p_wv,*p_wo,*p_w1,*p_w3,*p_w2;
    cudaGetSymbolAddress((void**)&p_xnh, g_xnh);
    cudaGetSymbolAddress((void**)&p_q,   g_q);
    cudaGetSymbolAddress((void**)&p_k,   g_k);
    cudaGetSymbolAddress((void**)&p_v,   g_v);
    cudaGetSymbolAddress((void**)&p_aoh, g_aoh);
    cudaGetSymbolAddress((void**)&p_h,   g_h);
    cudaGetSymbolAddress((void**)&p_ffnh,g_ffnh);
    cudaGetSymbolAddress((void**)&p_g1h, g_g1h);
    cudaGetSymbolAddress((void**)&p_wq,  g_wq);
    cudaGetSymbolAddress((void**)&p_wk,  g_wk);
    cudaGetSymbolAddress((void**)&p_wv,  g_wv);
    cudaGetSymbolAddress((void**)&p_wo,  g_wo);
    cudaGetSymbolAddress((void**)&p_w1,  g_w1);
    cudaGetSymbolAddress((void**)&p_w3,  g_w3);
    cudaGetSymbolAddress((void**)&p_w2,  g_w2);

    cudaFuncSetAttribute(gemm_h, cudaFuncAttributeMaxDynamicSharedMemorySize, SMEM_H);
    cudaFuncSetAttribute(gemm_ff, cudaFuncAttributeMaxDynamicSharedMemorySize, SMEM_F);
    cudaFuncSetAttribute(flash_attn, cudaFuncAttributeMaxDynamicSharedMemorySize, FLASH_SMEM);

    // 0. transpose + fp16 weights; init invf
    transpose_h<<<dim3(64,64,4), dim3(32,8)>>>(wq,p_wq, wk,p_wk, wv,p_wv, wo,p_wo,
                                               HIDDEN, HIDDEN, 1);
    transpose_h<<<dim3(176,64,2), dim3(32,8)>>>(w1,p_w1, w3,p_w3, nullptr,nullptr,
                                                nullptr,nullptr, HIDDEN, FFDIM, 0);
    transpose_h<<<dim3(64,176,1), dim3(32,8)>>>(w2,p_w2, nullptr,nullptr, nullptr,nullptr,
                                                nullptr,nullptr, FFDIM, HIDDEN, 0);

    // 1. rmsnorm (attn) -> fp16
    rmsnorm_h<<<NTOK,256>>>(x, asc, p_xnh);

    // 2-4. Q/K/V projections (rope fused into Q,K)
    dim3 gProj(32*16, 1, 1);
    gemm_h<<<gProj,256,SMEM_H>>>(p_xnh,HIDDEN, p_wq,HIDDEN, p_q,HIDDEN,
                                 nullptr, HIDDEN, 32,16, 0, pos, 1);
    gemm_h<<<gProj,256,SMEM_H>>>(p_xnh,HIDDEN, p_wk,HIDDEN, p_k,HIDDEN,
                                 nullptr, HIDDEN, 32,16, 0, pos, 1);
    gemm_h<<<gProj,256,SMEM_H>>>(p_xnh,HIDDEN, p_wv,HIDDEN, p_v,HIDDEN,
                                 nullptr, HIDDEN, 32,16, 1, nullptr, 0);

    // 5. flash attention (tf32; fp16 out)
    flash_attn<<<dim3(16, BATCHN*NHEADS),256,FLASH_SMEM>>>(
        p_q, p_k, p_v, p_aoh, 0.08838834764831845f);

    // 6. h = x + attn_out @ wo
    gemm_h<<<gProj,256,SMEM_H>>>(p_aoh,HIDDEN, p_wo,HIDDEN, p_h,HIDDEN,
                                 x, HIDDEN, 32,16, 0, nullptr, 0);

    // 7. rmsnorm (ffn) -> fp16
    rmsnorm_h<<<NTOK,256>>>(p_h, fsc, p_ffnh);

    // 8. fused FFN up+gate+silu -> g1h  (npn = 5632/64 = 88)
    dim3 gFF(32*88, 1, 1);
    gemm_ff<<<gFF,256,SMEM_F>>>(p_ffnh,HIDDEN, p_w1,p_w3,HIDDEN, p_g1h,FFDIM,
                                HIDDEN, 32,88);

    // 9. out = h + g1h @ w2  (K = 5632)
    gemm_h<<<gProj,256,SMEM_H>>>(p_g1h,FFDIM, p_w2,FFDIM, out,HIDDEN,
                                 p_h, FFDIM, 32,16, 0, nullptr, 0);
}

// round 10
// speedup vs baseline: 1.9353x; 1.1153x over previous
#include <cuda_runtime.h>
#include <cuda_fp16.h>
#include <cstdint>
#include <math.h>

#define HIDDEN 2048
#define NHEADS 16
#define HDIM 128
#define FFDIM 5632
#define BATCHN 2
#define SEQ 2048
#define NTOK (BATCHN*SEQ)   // 4096

// ---------------- scratch ----------------
__device__ __half g_xnh[NTOK*HIDDEN];
__device__ __half g_qh[NTOK*HIDDEN];
__device__ __half g_kh[NTOK*HIDDEN];
__device__ __half g_vth[BATCHN*NHEADS*HDIM*SEQ];   // V transposed: [b,h,dim,seq]
__device__ __half g_aoh[NTOK*HIDDEN];
__device__ float  g_h[NTOK*HIDDEN];
__device__ __half g_ffnh[NTOK*HIDDEN];
__device__ __half g_g1h[(size_t)NTOK*FFDIM];
__device__ float  g_invf[64];
// fp16 TRANSPOSED weights [N, K] K-major
__device__ __half g_wqkv[3*HIDDEN*HIDDEN];         // wq | wk | wv concatenated
__device__ __half g_wo[HIDDEN*HIDDEN];
__device__ __half g_w1[(size_t)HIDDEN*FFDIM];
__device__ __half g_w3[(size_t)HIDDEN*FFDIM];
__device__ __half g_w2[(size_t)FFDIM*HIDDEN];

// ---------------- helpers ----------------
__device__ __forceinline__ float rna_tf32(float x){
    unsigned r; asm("cvt.rna.tf32.f32 %0, %1;" : "=r"(r) : "f"(x));
    return __uint_as_float(r);
}
__device__ __forceinline__ unsigned smem_u32(const void* p){
    return (unsigned)__cvta_generic_to_shared(p);
}
__device__ __forceinline__ void cp16(unsigned s, const void* g){
    asm volatile("cp.async.cg.shared.global [%0], [%1], 16;\n" :: "r"(s), "l"(g));
}
#define CP_COMMIT() asm volatile("cp.async.commit_group;\n")
#define CP_WAIT(n)  asm volatile("cp.async.wait_group %0;\n" :: "n"(n))

__device__ __forceinline__ void mma_h(float c[4],
        unsigned a0, unsigned a1, unsigned a2, unsigned a3,
        unsigned b0, unsigned b1){
    asm volatile("mma.sync.aligned.m16n8k16.row.col.f32.f16.f16.f32 "
        "{%0,%1,%2,%3},{%4,%5,%6,%7},{%8,%9},{%0,%1,%2,%3};\n"
        : "+f"(c[0]), "+f"(c[1]), "+f"(c[2]), "+f"(c[3])
        : "r"(a0), "r"(a1), "r"(a2), "r"(a3), "r"(b0), "r"(b1));
}

__device__ __forceinline__ float warpReduceSum(float v){
    #pragma unroll
    for (int o=16;o;o>>=1) v += __shfl_xor_sync(0xffffffffu, v, o);
    return v;
}
__device__ float blockReduceSum(float v){   // 256 threads
    __shared__ float s[8]; __shared__ float tot;
    int lane = threadIdx.x & 31, w = threadIdx.x >> 5;
    v = warpReduceSum(v);
    if (!lane) s[w] = v;
    __syncthreads();
    if (w == 0){
        float t = (lane < 8) ? s[lane] : 0.f;
        t = warpReduceSum(t);
        if (!lane) tot = t;
    }
    __syncthreads();
    return tot;
}

// ======== fp16 GEMM (3-stage pipeline): C[M,N](f32) = A @ Bt^T (+ Res) ========
#define HSTR 72
#define HTILE (128*HSTR)
#define SMEM_H (3*2*HTILE*2)             // 110592 B

__global__ void __launch_bounds__(256, 2)
gemm_h(const __half* __restrict__ A, int lda,
       const __half* __restrict__ Bt, int ldb,
       float* __restrict__ C, int ldc,
       const float* __restrict__ Res,
       int K, int npm, int npn)
{
    extern __shared__ __half sh[];

    int pid = blockIdx.x;
    const int GROUP = 16;
    int npg = GROUP * npn;
    int gid = pid / npg;
    int firstm = gid * GROUP;
    int gsz = min(GROUP, npm - firstm);
    int pm = firstm + (pid % npg) % gsz;
    int pn = (pid % npg) / gsz;
    int m0 = pm * 128, n0 = pn * 128;

    int KT = K / 64;
    int tid = threadIdx.x;
    int wid = tid >> 5, lane = tid & 31;
    int wm = (wid & 3) * 32;
    int wn = (wid >> 2) * 64;
    int rl = lane >> 2, l3 = lane & 3;

    auto loadAB = [&](int st, int kt){
        __half* sa = sh + st * (2*HTILE);
        __half* sb = sa + HTILE;
        int c = tid & 7;
        int r0 = tid >> 3;
        const __half* ga = A  + (long long)m0 * lda + kt * 64 + c * 8;
        const __half* gb = Bt + (long long)n0 * ldb + kt * 64 + c * 8;
        #pragma unroll
        for (int w = 0; w < 4; w++){
            int row = r0 + 32 * w;
            cp16(smem_u32(sa + row * HSTR + c * 8), ga + (long long)row * lda);
        }
        #pragma unroll
        for (int w = 0; w < 4; w++){
            int row = r0 + 32 * w;
            cp16(smem_u32(sb + row * HSTR + c * 8), gb + (long long)row * ldb);
        }
    };

    float acc[2][8][4];
    #pragma unroll
    for (int i=0;i<2;i++)
        #pragma unroll
        for (int j=0;j<8;j++)
            #pragma unroll
            for (int r=0;r<4;r++) acc[i][j][r] = 0.f;

    loadAB(0, 0); CP_COMMIT();
    if (KT > 1) loadAB(1, 1);
    CP_COMMIT();

    for (int kt = 0; kt < KT; kt++){
        int cur = kt % 3;
        CP_WAIT(1);
        __syncthreads();
        if (kt + 2 < KT) loadAB((kt + 2) % 3, kt + 2);
        CP_COMMIT();

        const __half* sa = sh + cur * (2*HTILE);
        const __half* sb = sa + HTILE;
        #pragma unroll
        for (int ks = 0; ks < 4; ks++){
            int kk = ks * 16;
            unsigned a[2][4];
            #pragma unroll
            for (int mi = 0; mi < 2; mi++){
                const __half* ap = sa + (wm + mi * 16 + rl) * HSTR + kk + l3 * 2;
                a[mi][0] = *(const unsigned*)(ap);
                a[mi][1] = *(const unsigned*)(ap + 8 * HSTR);
                a[mi][2] = *(const unsigned*)(ap + 8);
                a[mi][3] = *(const unsigned*)(ap + 8 * HSTR + 8);
            }
            #pragma unroll
            for (int ni = 0; ni < 8; ni++){
                const __half* bp = sb + (wn + ni * 8 + rl) * HSTR + kk + l3 * 2;
                unsigned b0 = *(const unsigned*)(bp);
                unsigned b1 = *(const unsigned*)(bp + 8);
                #pragma unroll
                for (int mi = 0; mi < 2; mi++)
                    mma_h(acc[mi][ni], a[mi][0], a[mi][1], a[mi][2], a[mi][3], b0, b1);
            }
        }
    }

    #pragma unroll
    for (int mi = 0; mi < 2; mi++){
        #pragma unroll
        for (int ni = 0; ni < 8; ni++){
            int row = m0 + wm + mi * 16 + rl;
            int col = n0 + wn + ni * 8 + l3 * 2;
            float v0 = acc[mi][ni][0];
            float v1 = acc[mi][ni][1];
            float v2 = acc[mi][ni][2];
            float v3 = acc[mi][ni][3];
            if (Res){
                float2 r01 = *(const float2*)(Res + (long long)row * ldc + col);
                float2 r23 = *(const float2*)(Res + (long long)(row + 8) * ldc + col);
                v0 += r01.x; v1 += r01.y; v2 += r23.x; v3 += r23.y;
            }
            *(float2*)(C + (long long)row * ldc + col)       = make_float2(v0, v1);
            *(float2*)(C + (long long)(row + 8) * ldc + col) = make_float2(v2, v3);
        }
    }
}

// ======== merged QKV gemm: N=6144 over wqkv; epilogue rope->fp16 / V-transpose ===
__global__ void __launch_bounds__(256, 2)
gemm_qkv(const __half* __restrict__ A, int lda,
         const __half* __restrict__ Bt, int ldb,
         __half* __restrict__ Qh, __half* __restrict__ Kh, __half* __restrict__ Vt,
         const int* __restrict__ pos, int K, int npm, int npn)
{
    extern __shared__ __half sh[];

    int pid = blockIdx.x;
    const int GROUP = 16;
    int npg = GROUP * npn;
    int gid = pid / npg;
    int firstm = gid * GROUP;
    int gsz = min(GROUP, npm - firstm);
    int pm = firstm + (pid % npg) % gsz;
    int pn = (pid % npg) / gsz;
    int m0 = pm * 128, n0 = pn * 128;

    int KT = K / 64;
    int tid = threadIdx.x;
    int wid = tid >> 5, lane = tid & 31;
    int wm = (wid & 3) * 32;
    int wn = (wid >> 2) * 64;
    int rl = lane >> 2, l3 = lane & 3;

    auto loadAB = [&](int st, int kt){
        __half* sa = sh + st * (2*HTILE);
        __half* sb = sa + HTILE;
        int c = tid & 7;
        int r0 = tid >> 3;
        const __half* ga = A  + (long long)m0 * lda + kt * 64 + c * 8;
        const __half* gb = Bt + (long long)n0 * ldb + kt * 64 + c * 8;
        #pragma unroll
        for (int w = 0; w < 4; w++){
            int row = r0 + 32 * w;
            cp16(smem_u32(sa + row * HSTR + c * 8), ga + (long long)row * lda);
        }
        #pragma unroll
        for (int w = 0; w < 4; w++){
            int row = r0 + 32 * w;
            cp16(smem_u32(sb + row * HSTR + c * 8), gb + (long long)row * ldb);
        }
    };

    float acc[2][8][4];
    #pragma unroll
    for (int i=0;i<2;i++)
        #pragma unroll
        for (int j=0;j<8;j++)
            #pragma unroll
            for (int r=0;r<4;r++) acc[i][j][r] = 0.f;

    loadAB(0, 0); CP_COMMIT();
    if (KT > 1) loadAB(1, 1);
    CP_COMMIT();

    for (int kt = 0; kt < KT; kt++){
        int cur = kt % 3;
        CP_WAIT(1);
        __syncthreads();
        if (kt + 2 < KT) loadAB((kt + 2) % 3, kt + 2);
        CP_COMMIT();

        const __half* sa = sh + cur * (2*HTILE);
        const __half* sb = sa + HTILE;
        #pragma unroll
        for (int ks = 0; ks < 4; ks++){
            int kk = ks * 16;
            unsigned a[2][4];
            #pragma unroll
            for (int mi = 0; mi < 2; mi++){
                const __half* ap = sa + (wm + mi * 16 + rl) * HSTR + kk + l3 * 2;
                a[mi][0] = *(const unsigned*)(ap);
                a[mi][1] = *(const unsigned*)(ap + 8 * HSTR);
                a[mi][2] = *(const unsigned*)(ap + 8);
                a[mi][3] = *(const unsigned*)(ap + 8 * HSTR + 8);
            }
            #pragma unroll
            for (int ni = 0; ni < 8; ni++){
                const __half* bp = sb + (wn + ni * 8 + rl) * HSTR + kk + l3 * 2;
                unsigned b0 = *(const unsigned*)(bp);
                unsigned b1 = *(const unsigned*)(bp + 8);
                #pragma unroll
                for (int mi = 0; mi < 2; mi++)
                    mma_h(acc[mi][ni], a[mi][0], a[mi][1], a[mi][2], a[mi][3], b0, b1);
            }
        }
    }

    int wsel = n0 >> 11;          // 0=q, 1=k, 2=v
    int n0l  = n0 & 2047;
    #pragma unroll
    for (int mi = 0; mi < 2; mi++){
        #pragma unroll
        for (int ni = 0; ni < 8; ni++){
            int row = m0 + wm + mi * 16 + rl;
            int col = n0l + wn + ni * 8 + l3 * 2;
            float v0 = acc[mi][ni][0];
            float v1 = acc[mi][ni][1];
            float v2 = acc[mi][ni][2];
            float v3 = acc[mi][ni][3];
            if (wsel < 2){
                // rope then fp16
                int i = (col & 127) >> 1;
                float invf = g_invf[i];
                float a0 = (float)pos[row] * invf;
                float a1 = (float)pos[row + 8] * invf;
                float s0, c0, s1, c1;
                sincosf(a0, &s0, &c0);
                sincosf(a1, &s1, &c1);
                float t0 = v0 * c0 - v1 * s0;
                float t1 = v1 * c0 + v0 * s0;
                float t2 = v2 * c1 - v3 * s1;
                float t3 = v3 * c1 + v2 * s1;
                __half* O = wsel ? Kh : Qh;
                *(__half2*)(O + (long long)row * 2048 + col)       = __floats2half2_rn(t0, t1);
                *(__half2*)(O + (long long)(row + 8) * 2048 + col) = __floats2half2_rn(t2, t3);
            } else {
                // V transposed: Vt[(b*16+h)*128 + dim][seq]
                int b = row >> 11, seq = row & 2047;
                int h = col >> 7,  dim = col & 127;
                __half* base = Vt + ((long long)(b * 16 + h) * 128) * 2048;
                base[(long long)dim * 2048 + seq]           = __float2half_rn(v0);
                base[(long long)(dim + 1) * 2048 + seq]     = __float2half_rn(v1);
                base[(long long)dim * 2048 + seq + 8]       = __float2half_rn(v2);
                base[(long long)(dim + 1) * 2048 + seq + 8] = __float2half_rn(v3);
            }
        }
    }
}

// ======== fused FFN: g1h = fp16( silu(A@W1^T) * (A@W3^T) ) ========
#define FBTILE (64*HSTR)
#define FSTAGE (HTILE + 2*FBTILE)
#define SMEM_F (3*FSTAGE*2)              // 110592 B

__global__ void __launch_bounds__(256, 2)
gemm_ff(const __half* __restrict__ A, int lda,
        const __half* __restrict__ B1t, const __half* __restrict__ B3t, int ldb,
        __half* __restrict__ O, int ldo,
        int K, int npm, int npn)
{
    extern __shared__ __half sh[];

    int pid = blockIdx.x;
    const int GROUP = 16;
    int npg = GROUP * npn;
    int gid = pid / npg;
    int firstm = gid * GROUP;
    int gsz = min(GROUP, npm - firstm);
    int pm = firstm + (pid % npg) % gsz;
    int pn = (pid % npg) / gsz;
    int m0 = pm * 128, n0 = pn * 64;

    int KT = K / 64;
    int tid = threadIdx.x;
    int wid = tid >> 5, lane = tid & 31;
    int wm = (wid & 3) * 32;
    int wn = (wid >> 2) * 32;
    int rl = lane >> 2, l3 = lane & 3;

    auto loadAB = [&](int st, int kt){
        __half* sa = sh + st * FSTAGE;
        __half* sb1 = sa + HTILE;
        __half* sb3 = sb1 + FBTILE;
        int c = tid & 7;
        int r0 = tid >> 3;
        const __half* ga = A + (long long)m0 * lda + kt * 64 + c * 8;
        #pragma unroll
        for (int w = 0; w < 4; w++){
            int row = r0 + 32 * w;
            cp16(smem_u32(sa + row * HSTR + c * 8), ga + (long long)row * lda);
        }
        const __half* g1 = B1t + (long long)n0 * ldb + kt * 64 + c * 8;
        const __half* g3 = B3t + (long long)n0 * ldb + kt * 64 + c * 8;
        #pragma unroll
        for (int w = 0; w < 2; w++){
            int row = r0 + 32 * w;
            cp16(smem_u32(sb1 + row * HSTR + c * 8), g1 + (long long)row * ldb);
        }
        #pragma unroll
        for (int w = 0; w < 2; w++){
            int row = r0 + 32 * w;
            cp16(smem_u32(sb3 + row * HSTR + c * 8), g3 + (long long)row * ldb);
        }
    };

    float ac1[2][4][4], ac3[2][4][4];
    #pragma unroll
    for (int i=0;i<2;i++)
        #pragma unroll
        for (int j=0;j<4;j++)
            #pragma unroll
            for (int r=0;r<4;r++){ ac1[i][j][r] = 0.f; ac3[i][j][r] = 0.f; }

    loadAB(0, 0); CP_COMMIT();
    if (KT > 1) loadAB(1, 1);
    CP_COMMIT();

    for (int kt = 0; kt < KT; kt++){
        int cur = kt % 3;
        CP_WAIT(1);
        __syncthreads();
        if (kt + 2 < KT) loadAB((kt + 2) % 3, kt + 2);
        CP_COMMIT();

        const __half* sa  = sh + cur * FSTAGE;
        const __half* sb1 = sa + HTILE;
        const __half* sb3 = sb1 + FBTILE;
        #pragma unroll
        for (int ks = 0; ks < 4; ks++){
            int kk = ks * 16;
            unsigned a[2][4];
            #pragma unroll
            for (int mi = 0; mi < 2; mi++){
                const __half* ap = sa + (wm + mi * 16 + rl) * HSTR + kk + l3 * 2;
                a[mi][0] = *(const unsigned*)(ap);
                a[mi][1] = *(const unsigned*)(ap + 8 * HSTR);
                a[mi][2] = *(const unsigned*)(ap + 8);
                a[mi][3] = *(const unsigned*)(ap + 8 * HSTR + 8);
            }
            #pragma unroll
            for (int ni = 0; ni < 4; ni++){
                const __half* b1p = sb1 + (wn + ni * 8 + rl) * HSTR + kk + l3 * 2;
                const __half* b3p = sb3 + (wn + ni * 8 + rl) * HSTR + kk + l3 * 2;
                unsigned b10 = *(const unsigned*)(b1p);
                unsigned b11 = *(const unsigned*)(b1p + 8);
                unsigned b30 = *(const unsigned*)(b3p);
                unsigned b31 = *(const unsigned*)(b3p + 8);
                #pragma unroll
                for (int mi = 0; mi < 2; mi++){
                    mma_h(ac1[mi][ni], a[mi][0], a[mi][1], a[mi][2], a[mi][3], b10, b11);
                    mma_h(ac3[mi][ni], a[mi][0], a[mi][1], a[mi][2], a[mi][3], b30, b31);
                }
            }
        }
    }

    #pragma unroll
    for (int mi = 0; mi < 2; mi++){
        #pragma unroll
        for (int ni = 0; ni < 4; ni++){
            int row = m0 + wm + mi * 16 + rl;
            int col = n0 + wn + ni * 8 + l3 * 2;
            float x0 = ac1[mi][ni][0], x1 = ac1[mi][ni][1];
            float x2 = ac1[mi][ni][2], x3 = ac1[mi][ni][3];
            float y0 = ac3[mi][ni][0], y1 = ac3[mi][ni][1];
            float y2 = ac3[mi][ni][2], y3 = ac3[mi][ni][3];
            float s0 = x0 / (1.0f + __expf(-x0)) * y0;
            float s1 = x1 / (1.0f + __expf(-x1)) * y1;
            float s2 = x2 / (1.0f + __expf(-x2)) * y2;
            float s3 = x3 / (1.0f + __expf(-x3)) * y3;
            *(__half2*)(O + (long long)row * ldo + col)       = __floats2half2_rn(s0, s1);
            *(__half2*)(O + (long long)(row + 8) * ldo + col) = __floats2half2_rn(s2, s3);
        }
    }
}

// ---------------- flash attention v3: full fp16, 128-key tiles ----------------
// Per CTA: one (b,h), one 128-row q tile. 8 warps x 16 q rows.
// smem: K [2][128][136]h, Vt [2][128][136]h, P [8][16][136]h  = 174080 B
#define FKSTR 136
#define FLASH_SMEM ((2*128*FKSTR + 2*128*FKSTR + 8*16*FKSTR)*2)

__global__ void __launch_bounds__(256, 1)
flash_h(const __half* __restrict__ Q, const __half* __restrict__ K,
        const __half* __restrict__ Vt, __half* __restrict__ O,
        float alpha)
{
    extern __shared__ __half sh[];
    __half* sKb  = sh;                        // 2 x 128*136
    __half* sVtb = sh + 2*128*FKSTR;          // 2 x 128*136
    __half* sP   = sVtb + 2*128*FKSTR;        // 8 x 16*136

    int z = blockIdx.y;                // b*16+h
    int b = z >> 4, h = z & 15;
    int qt = (gridDim.x - 1) - blockIdx.x;    // heavy tiles first
    int q0 = qt * 128;
    const __half* Qg  = Q + ((long long)b * SEQ) * HIDDEN + h * HDIM;
    const __half* Kg  = K + ((long long)b * SEQ) * HIDDEN + h * HDIM;
    const __half* Vtg = Vt + ((long long)z * HDIM) * SEQ;
    __half* Og = O + ((long long)b * SEQ) * HIDDEN + h * HDIM;

    int tid = threadIdx.x, wid = tid >> 5, lane = tid & 31;
    int rl = lane >> 2, l3 = lane & 3;
    int qr = q0 + wid * 16;
    __half* sPw = sP + wid * 16 * FKSTR;

    // Q fragments (fp16): 8 k16 steps x 4 regs
    unsigned qf[8][4];
    #pragma unroll
    for (int ks = 0; ks < 8; ks++){
        const __half* p0 = Qg + (long long)(qr + rl) * HIDDEN + ks * 16 + l3 * 2;
        const __half* p1 = Qg + (long long)(qr + rl + 8) * HIDDEN + ks * 16 + l3 * 2;
        qf[ks][0] = *(const unsigned*)(p0);
        qf[ks][1] = *(const unsigned*)(p1);
        qf[ks][2] = *(const unsigned*)(p0 + 8);
        qf[ks][3] = *(const unsigned*)(p1 + 8);
    }

    float Oa[16][4];
    #pragma unroll
    for (int ni = 0; ni < 16; ni++){
        Oa[ni][0] = 0.f; Oa[ni][1] = 0.f; Oa[ni][2] = 0.f; Oa[ni][3] = 0.f;
    }
    float m0r = -1e30f, m1r = -1e30f, l0r = 0.f, l1r = 0.f;

    // one commit group per tile: K rows (keys x dims) + Vt rows (dims x keys)
    auto loadKV = [&](int buf, int t){
        int c = tid & 15, r0 = tid >> 4;          // 16 chunks/row, 16 rows/pass
        const __half* kp = Kg + (long long)(t * 128) * HIDDEN + c * 8;
        __half* dk = sKb + buf * 128 * FKSTR;
        #pragma unroll
        for (int w = 0; w < 8; w++){
            int row = r0 + 16 * w;
            cp16(smem_u32(dk + row * FKSTR + c * 8), kp + (long long)row * HIDDEN);
        }
        const __half* vp = Vtg + t * 128 + c * 8;
        __half* dv = sVtb + buf * 128 * FKSTR;
        #pragma unroll
        for (int w = 0; w < 8; w++){
            int row = r0 + 16 * w;                // dim index
            cp16(smem_u32(dv + row * FKSTR + c * 8), vp + (long long)row * SEQ);
        }
    };

    int nt = qt + 1;
    loadKV(0, 0); CP_COMMIT();

    for (int t = 0; t < nt; t++){
        int buf = t & 1;
        if (t + 1 < nt){
            loadKV(buf ^ 1, t + 1);
            CP_COMMIT();
            CP_WAIT(1);
        } else {
            CP_WAIT(0);
        }
        __syncthreads();
        const __half* cK  = sKb  + buf * 128 * FKSTR;
        const __half* cVt = sVtb + buf * 128 * FKSTR;
        int diag = (t == qt);
        int k0 = t * 128;

        // S = Q @ K^T over 128 keys (16 n-frags)
        float Sa[16][4];
        #pragma unroll
        for (int ni = 0; ni < 16; ni++){
            Sa[ni][0]=0.f; Sa[ni][1]=0.f; Sa[ni][2]=0.f; Sa[ni][3]=0.f;
        }
        #pragma unroll
        for (int ks = 0; ks < 8; ks++){
            int kk = ks * 16;
            #pragma unroll
            for (int ni = 0; ni < 16; ni++){
                const __half* bp = cK + (ni * 8 + rl) * FKSTR + kk + l3 * 2;
                unsigned b0 = *(const unsigned*)(bp);
                unsigned b1 = *(const unsigned*)(bp + 8);
                mma_h(Sa[ni], qf[ks][0], qf[ks][1], qf[ks][2], qf[ks][3], b0, b1);
            }
        }

        // scale + causal mask + row max
        int r0g = qr + rl, r1g = qr + rl + 8;
        float mx0 = -1e30f, mx1 = -1e30f;
        #pragma unroll
        for (int ni = 0; ni < 16; ni++){
            float x0 = Sa[ni][0] * alpha, x1 = Sa[ni][1] * alpha;
            float x2 = Sa[ni][2] * alpha, x3 = Sa[ni][3] * alpha;
            if (diag){
                int kg = k0 + ni * 8 + 2 * l3;
                if (kg     > r0g) x0 = -1e30f;
                if (kg + 1 > r0g) x1 = -1e30f;
                if (kg     > r1g) x2 = -1e30f;
                if (kg + 1 > r1g) x3 = -1e30f;
            }
            Sa[ni][0]=x0; Sa[ni][1]=x1; Sa[ni][2]=x2; Sa[ni][3]=x3;
            mx0 = fmaxf(mx0, fmaxf(x0, x1));
            mx1 = fmaxf(mx1, fmaxf(x2, x3));
        }
        mx0 = fmaxf(mx0, __shfl_xor_sync(0xffffffffu, mx0, 1));
        mx0 = fmaxf(mx0, __shfl_xor_sync(0xffffffffu, mx0, 2));
        mx1 = fmaxf(mx1, __shfl_xor_sync(0xffffffffu, mx1, 1));
        mx1 = fmaxf(mx1, __shfl_xor_sync(0xffffffffu, mx1, 2));

        float mn0 = fmaxf(m0r, mx0), mn1 = fmaxf(m1r, mx1);
        float cr0 = __expf(m0r - mn0), cr1 = __expf(m1r - mn1);
        m0r = mn0; m1r = mn1;
        l0r *= cr0; l1r *= cr1;
        #pragma unroll
        for (int ni = 0; ni < 16; ni++){
            Oa[ni][0] *= cr0; Oa[ni][1] *= cr0;
            Oa[ni][2] *= cr1; Oa[ni][3] *= cr1;
        }
        float rs0 = 0.f, rs1 = 0.f;
        #pragma unroll
        for (int ni = 0; ni < 16; ni++){
            float e0 = __expf(Sa[ni][0] - mn0);
            float e1 = __expf(Sa[ni][1] - mn0);
            float e2 = __expf(Sa[ni][2] - mn1);
            float e3 = __expf(Sa[ni][3] - mn1);
            rs0 += e0 + e1; rs1 += e2 + e3;
            int colp = ni * 8 + 2 * l3;
            *(__half2*)(sPw + rl * FKSTR + colp)       = __floats2half2_rn(e0, e1);
            *(__half2*)(sPw + (rl + 8) * FKSTR + colp) = __floats2half2_rn(e2, e3);
        }
        rs0 += __shfl_xor_sync(0xffffffffu, rs0, 1);
        rs0 += __shfl_xor_sync(0xffffffffu, rs0, 2);
        rs1 += __shfl_xor_sync(0xffffffffu, rs1, 1);
        rs1 += __shfl_xor_sync(0xffffffffu, rs1, 2);
        l0r += rs0; l1r += rs1;
        __syncwarp();

        // O += P @ V : k = 128 keys (8 k16 steps), n = 128 dims (16 frags)
        #pragma unroll
        for (int ks = 0; ks < 8; ks++){
            int kk = ks * 16;
            const __half* ap0 = sPw + rl * FKSTR + kk + l3 * 2;
            const __half* ap1 = sPw + (rl + 8) * FKSTR + kk + l3 * 2;
            unsigned a0 = *(const unsigned*)(ap0);
            unsigned a1 = *(const unsigned*)(ap1);
            unsigned a2 = *(const unsigned*)(ap0 + 8);
            unsigned a3 = *(const unsigned*)(ap1 + 8);
            #pragma unroll
            for (int ni = 0; ni < 16; ni++){
                const __half* bp = cVt + (ni * 8 + rl) * FKSTR + kk + l3 * 2;
                unsigned b0 = *(const unsigned*)(bp);
                unsigned b1 = *(const unsigned*)(bp + 8);
                mma_h(Oa[ni], a0, a1, a2, a3, b0, b1);
            }
        }
        __syncthreads();   // all warps done with cK/cVt before prefetch overwrites
    }

    // normalize + write fp16
    float inv0 = 1.0f / l0r, inv1 = 1.0f / l1r;
    #pragma unroll
    for (int ni = 0; ni < 16; ni++){
        int col = ni * 8 + 2 * l3;
        *(__half2*)(Og + (long long)(qr + rl) * HIDDEN + col) =
            __floats2half2_rn(Oa[ni][0] * inv0, Oa[ni][1] * inv0);
        *(__half2*)(Og + (long long)(qr + rl + 8) * HIDDEN + col) =
            __floats2half2_rn(Oa[ni][2] * inv1, Oa[ni][3] * inv1);
    }
}

// ---------------- transpose + fp16 ----------------
__global__ void transpose_h(const float* s0, __half* d0, const float* s1, __half* d1,
                            const float* s2, __half* d2, const float* s3, __half* d3,
                            int R, int C, int doInvf)
{
    __shared__ float t[32][33];
    const float* in; __half* out;
    switch (blockIdx.z){
        case 0:  in = s0; out = d0; break;
        case 1:  in = s1; out = d1; break;
        case 2:  in = s2; out = d2; break;
        default: in = s3; out = d3; break;
    }
    if (doInvf && blockIdx.x == 0 && blockIdx.y == 0 && blockIdx.z == 0){
        int f = threadIdx.y * 32 + threadIdx.x;
        if (f < 64) g_invf[f] = (float)exp(-(double)f * (log(500000.0) / 64.0));
    }
    int x  = blockIdx.x * 32 + threadIdx.x;
    int y0 = blockIdx.y * 32 + threadIdx.y;
    #pragma unroll
    for (int dy = 0; dy < 32; dy += 8)
        t[threadIdx.y + dy][threadIdx.x] = in[(long long)(y0 + dy) * C + x];
    __syncthreads();
    int ox  = blockIdx.y * 32 + threadIdx.x;
    int oy0 = blockIdx.x * 32 + threadIdx.y;
    #pragma unroll
    for (int dy = 0; dy < 32; dy += 8)
        out[(long long)(oy0 + dy) * R + ox] = __float2half_rn(t[threadIdx.x][threadIdx.y + dy]);
}

__global__ void rmsnorm_h(const float* __restrict__ X, const float* __restrict__ sc,
                          __half* __restrict__ O){
    long long base = (long long)blockIdx.x * HIDDEN;
    int tid = threadIdx.x;
    float v[8]; float ss = 0.f;
    #pragma unroll
    for (int i = 0; i < 8; i++){
        v[i] = X[base + tid + i * 256];
        ss += v[i] * v[i];
    }
    ss = blockReduceSum(ss);
    float r = rsqrtf(ss * (1.0f / (float)HIDDEN) + 1e-5f);
    #pragma unroll
    for (int i = 0; i < 8; i++){
        int c = tid + i * 256;
        O[base + c] = __float2half_rn(v[i] * r * sc[c]);
    }
}

// ---------------- launch ----------------
extern "C" void kernel_launch(void* const* d_in, const int* in_sizes, int n_in,
                              void* d_out, int out_size)
{
    const float* x   = (const float*)d_in[0];
    const int*   pos = (const int*)d_in[1];
    // d_in[2] = mask (causal; handled analytically)
    const float* wq  = (const float*)d_in[3];
    const float* wk  = (const float*)d_in[4];
    const float* wv  = (const float*)d_in[5];
    const float* wo  = (const float*)d_in[6];
    const float* asc = (const float*)d_in[7];
    const float* fsc = (const float*)d_in[8];
    const float* w1  = (const float*)d_in[9];
    const float* w3  = (const float*)d_in[10];
    const float* w2  = (const float*)d_in[11];
    float* out = (float*)d_out;

    __half *p_xnh,*p_qh,*p_kh,*p_vth,*p_aoh,*p_ffnh,*p_g1h;
    float *p_h;
    __half *p_wqkv,*p_wo,*p_w1,*p_w3,*p_w2;
    cudaGetSymbolAddress((void**)&p_xnh,  g_xnh);
    cudaGetSymbolAddress((void**)&p_qh,   g_qh);
    cudaGetSymbolAddress((void**)&p_kh,   g_kh);
    cudaGetSymbolAddress((void**)&p_vth,  g_vth);
    cudaGetSymbolAddress((void**)&p_aoh,  g_aoh);
    cudaGetSymbolAddress((void**)&p_h,    g_h);
    cudaGetSymbolAddress((void**)&p_ffnh, g_ffnh);
    cudaGetSymbolAddress((void**)&p_g1h,  g_g1h);
    cudaGetSymbolAddress((void**)&p_wqkv, g_wqkv);
    cudaGetSymbolAddress((void**)&p_wo,   g_wo);
    cudaGetSymbolAddress((void**)&p_w1,   g_w1);
    cudaGetSymbolAddress((void**)&p_w3,   g_w3);
    cudaGetSymbolAddress((void**)&p_w2,   g_w2);

    cudaFuncSetAttribute(gemm_h,   cudaFuncAttributeMaxDynamicSharedMemorySize, SMEM_H);
    cudaFuncSetAttribute(gemm_qkv, cudaFuncAttributeMaxDynamicSharedMemorySize, SMEM_H);
    cudaFuncSetAttribute(gemm_ff,  cudaFuncAttributeMaxDynamicSharedMemorySize, SMEM_F);
    cudaFuncSetAttribute(flash_h,  cudaFuncAttributeMaxDynamicSharedMemorySize, FLASH_SMEM);

    // 0. transpose + fp16 weights; wq|wk|wv concatenated into wqkv
    transpose_h<<<dim3(64,64,4), dim3(32,8)>>>(
        wq, p_wqkv,
        wk, p_wqkv + (size_t)HIDDEN*HIDDEN,
        wv, p_wqkv + (size_t)2*HIDDEN*HIDDEN,
        wo, p_wo, HIDDEN, HIDDEN, 1);
    transpose_h<<<dim3(176,64,2), dim3(32,8)>>>(w1,p_w1, w3,p_w3, nullptr,nullptr,
                                                nullptr,nullptr, HIDDEN, FFDIM, 0);
    transpose_h<<<dim3(64,176,1), dim3(32,8)>>>(w2,p_w2, nullptr,nullptr, nullptr,nullptr,
                                                nullptr,nullptr, FFDIM, HIDDEN, 0);

    // 1. rmsnorm (attn) -> fp16
    rmsnorm_h<<<NTOK,256>>>(x, asc, p_xnh);

    // 2. merged QKV projection (N=6144), rope->fp16 q/k, transposed fp16 v
    dim3 gQKV(32*48, 1, 1);
    gemm_qkv<<<gQKV,256,SMEM_H>>>(p_xnh,HIDDEN, p_wqkv,HIDDEN,
                                  p_qh, p_kh, p_vth, pos, HIDDEN, 32,48);

    // 3. flash attention (fp16; launch idx 5 -> profiled by ncu)
    flash_h<<<dim3(16, BATCHN*NHEADS),256,FLASH_SMEM>>>(
        p_qh, p_kh, p_vth, p_aoh, 0.08838834764831845f);

    // 4. h = x + attn_out @ wo
    dim3 gProj(32*16, 1, 1);
    gemm_h<<<gProj,256,SMEM_H>>>(p_aoh,HIDDEN, p_wo,HIDDEN, p_h,HIDDEN,
                                 x, HIDDEN, 32,16);

    // 5. rmsnorm (ffn) -> fp16
    rmsnorm_h<<<NTOK,256>>>(p_h, fsc, p_ffnh);

    // 6. fused FFN up+gate+silu -> g1h
    dim3 gFF(32*88, 1, 1);
    gemm_ff<<<gFF,256,SMEM_F>>>(p_ffnh,HIDDEN, p_w1,p_w3,HIDDEN, p_g1h,FFDIM,
                                HIDDEN, 32,88);

    // 7. out = h + g1h @ w2  (K = 5632)
    gemm_h<<<gProj,256,SMEM_H>>>(p_g1h,FFDIM, p_w2,FFDIM, out,HIDDEN,
                                 p_h, FFDIM, 32,16);
}

// round 11
// speedup vs baseline: 2.0718x; 1.0706x over previous
#include <cuda_runtime.h>
#include <cuda_fp16.h>
#include <cstdint>
#include <math.h>

#define HIDDEN 2048
#define NHEADS 16
#define HDIM 128
#define FFDIM 5632
#define BATCHN 2
#define SEQ 2048
#define NTOK (BATCHN*SEQ)   // 4096

// ---------------- scratch ----------------
__device__ __half g_xnh[NTOK*HIDDEN];
__device__ __half g_qh[NTOK*HIDDEN];
__device__ __half g_kh[NTOK*HIDDEN];
__device__ __half g_vth[BATCHN*NHEADS*HDIM*SEQ];   // V transposed: [b,h,dim,seq]
__device__ __half g_aoh[NTOK*HIDDEN];
__device__ float  g_h[NTOK*HIDDEN];
__device__ __half g_ffnh[NTOK*HIDDEN];
__device__ __half g_g1h[(size_t)NTOK*FFDIM];
__device__ float  g_invf[64];
// fp16 TRANSPOSED weights [N, K] K-major
__device__ __half g_wqkv[3*HIDDEN*HIDDEN];         // wq | wk | wv concatenated
__device__ __half g_wo[HIDDEN*HIDDEN];
__device__ __half g_w1[(size_t)HIDDEN*FFDIM];
__device__ __half g_w3[(size_t)HIDDEN*FFDIM];
__device__ __half g_w2[(size_t)FFDIM*HIDDEN];

// ---------------- helpers ----------------
__device__ __forceinline__ unsigned smem_u32(const void* p){
    return (unsigned)__cvta_generic_to_shared(p);
}
__device__ __forceinline__ void cp16(unsigned s, const void* g){
    asm volatile("cp.async.cg.shared.global [%0], [%1], 16;\n" :: "r"(s), "l"(g));
}
#define CP_COMMIT() asm volatile("cp.async.commit_group;\n")
#define CP_WAIT(n)  asm volatile("cp.async.wait_group %0;\n" :: "n"(n))

__device__ __forceinline__ void mma_h(float c[4],
        unsigned a0, unsigned a1, unsigned a2, unsigned a3,
        unsigned b0, unsigned b1){
    asm volatile("mma.sync.aligned.m16n8k16.row.col.f32.f16.f16.f32 "
        "{%0,%1,%2,%3},{%4,%5,%6,%7},{%8,%9},{%0,%1,%2,%3};\n"
        : "+f"(c[0]), "+f"(c[1]), "+f"(c[2]), "+f"(c[3])
        : "r"(a0), "r"(a1), "r"(a2), "r"(a3), "r"(b0), "r"(b1));
}
__device__ __forceinline__ void ldm_x4(unsigned &r0, unsigned &r1, unsigned &r2, unsigned &r3,
                                       unsigned addr){
    asm volatile("ldmatrix.sync.aligned.m8n8.x4.shared.b16 {%0,%1,%2,%3}, [%4];"
        : "=r"(r0), "=r"(r1), "=r"(r2), "=r"(r3) : "r"(addr));
}

__device__ __forceinline__ float warpReduceSum(float v){
    #pragma unroll
    for (int o=16;o;o>>=1) v += __shfl_xor_sync(0xffffffffu, v, o);
    return v;
}
__device__ float blockReduceSum(float v){   // 256 threads
    __shared__ float s[8]; __shared__ float tot;
    int lane = threadIdx.x & 31, w = threadIdx.x >> 5;
    v = warpReduceSum(v);
    if (!lane) s[w] = v;
    __syncthreads();
    if (w == 0){
        float t = (lane < 8) ? s[lane] : 0.f;
        t = warpReduceSum(t);
        if (!lane) tot = t;
    }
    __syncthreads();
    return tot;
}

// ======== fp16 GEMM (3-stage pipeline + ldmatrix): C[M,N](f32) = A @ Bt^T (+ Res) ==
#define HSTR 72
#define HTILE (128*HSTR)
#define SMEM_H (3*2*HTILE*2)             // 110592 B

__global__ void __launch_bounds__(256, 2)
gemm_h(const __half* __restrict__ A, int lda,
       const __half* __restrict__ Bt, int ldb,
       float* __restrict__ C, int ldc,
       const float* __restrict__ Res,
       int K, int npm, int npn)
{
    extern __shared__ __half sh[];

    int pid = blockIdx.x;
    const int GROUP = 16;
    int npg = GROUP * npn;
    int gid = pid / npg;
    int firstm = gid * GROUP;
    int gsz = min(GROUP, npm - firstm);
    int pm = firstm + (pid % npg) % gsz;
    int pn = (pid % npg) / gsz;
    int m0 = pm * 128, n0 = pn * 128;

    int KT = K / 64;
    int tid = threadIdx.x;
    int wid = tid >> 5, lane = tid & 31;
    int wm = (wid & 3) * 32;
    int wn = (wid >> 2) * 64;
    int rl = lane >> 2, l3 = lane & 3;

    // per-lane ldmatrix row offsets (in halves)
    int arow = (wm + (lane & 15)) * HSTR + (lane >> 4) * 8;           // + mi*16*HSTR
    int brow = (wn + (lane & 7) + ((lane >> 4) << 3)) * HSTR + (((lane >> 3) & 1) << 3); // + nip*16*HSTR

    auto loadAB = [&](int st, int kt){
        __half* sa = sh + st * (2*HTILE);
        __half* sb = sa + HTILE;
        int c = tid & 7;
        int r0 = tid >> 3;
        const __half* ga = A  + (long long)m0 * lda + kt * 64 + c * 8;
        const __half* gb = Bt + (long long)n0 * ldb + kt * 64 + c * 8;
        #pragma unroll
        for (int w = 0; w < 4; w++){
            int row = r0 + 32 * w;
            cp16(smem_u32(sa + row * HSTR + c * 8), ga + (long long)row * lda);
        }
        #pragma unroll
        for (int w = 0; w < 4; w++){
            int row = r0 + 32 * w;
            cp16(smem_u32(sb + row * HSTR + c * 8), gb + (long long)row * ldb);
        }
    };

    float acc[2][8][4];
    #pragma unroll
    for (int i=0;i<2;i++)
        #pragma unroll
        for (int j=0;j<8;j++)
            #pragma unroll
            for (int r=0;r<4;r++) acc[i][j][r] = 0.f;

    loadAB(0, 0); CP_COMMIT();
    if (KT > 1) loadAB(1, 1);
    CP_COMMIT();

    for (int kt = 0; kt < KT; kt++){
        int cur = kt % 3;
        CP_WAIT(1);
        __syncthreads();
        if (kt + 2 < KT) loadAB((kt + 2) % 3, kt + 2);
        CP_COMMIT();

        const __half* sa = sh + cur * (2*HTILE);
        const __half* sb = sa + HTILE;
        unsigned abase = smem_u32(sa) + arow * 2;
        unsigned bbase = smem_u32(sb) + brow * 2;
        #pragma unroll
        for (int ks = 0; ks < 4; ks++){
            unsigned koff = ks * 32;               // 16 halves = 32 B
            unsigned a[2][4];
            #pragma unroll
            for (int mi = 0; mi < 2; mi++)
                ldm_x4(a[mi][0], a[mi][1], a[mi][2], a[mi][3],
                       abase + mi * (16 * HSTR * 2) + koff);
            #pragma unroll
            for (int nip = 0; nip < 4; nip++){
                unsigned b0, b1, b2, b3;
                ldm_x4(b0, b1, b2, b3, bbase + nip * (16 * HSTR * 2) + koff);
                #pragma unroll
                for (int mi = 0; mi < 2; mi++){
                    mma_h(acc[mi][2*nip],   a[mi][0], a[mi][1], a[mi][2], a[mi][3], b0, b1);
                    mma_h(acc[mi][2*nip+1], a[mi][0], a[mi][1], a[mi][2], a[mi][3], b2, b3);
                }
            }
        }
    }

    #pragma unroll
    for (int mi = 0; mi < 2; mi++){
        #pragma unroll
        for (int ni = 0; ni < 8; ni++){
            int row = m0 + wm + mi * 16 + rl;
            int col = n0 + wn + ni * 8 + l3 * 2;
            float v0 = acc[mi][ni][0];
            float v1 = acc[mi][ni][1];
            float v2 = acc[mi][ni][2];
            float v3 = acc[mi][ni][3];
            if (Res){
                float2 r01 = *(const float2*)(Res + (long long)row * ldc + col);
                float2 r23 = *(const float2*)(Res + (long long)(row + 8) * ldc + col);
                v0 += r01.x; v1 += r01.y; v2 += r23.x; v3 += r23.y;
            }
            *(float2*)(C + (long long)row * ldc + col)       = make_float2(v0, v1);
            *(float2*)(C + (long long)(row + 8) * ldc + col) = make_float2(v2, v3);
        }
    }
}

// ======== merged QKV gemm (ldmatrix): N=6144; epilogue rope->fp16 / V-transpose ===
__global__ void __launch_bounds__(256, 2)
gemm_qkv(const __half* __restrict__ A, int lda,
         const __half* __restrict__ Bt, int ldb,
         __half* __restrict__ Qh, __half* __restrict__ Kh, __half* __restrict__ Vt,
         const int* __restrict__ pos, int K, int npm, int npn)
{
    extern __shared__ __half sh[];

    int pid = blockIdx.x;
    const int GROUP = 16;
    int npg = GROUP * npn;
    int gid = pid / npg;
    int firstm = gid * GROUP;
    int gsz = min(GROUP, npm - firstm);
    int pm = firstm + (pid % npg) % gsz;
    int pn = (pid % npg) / gsz;
    int m0 = pm * 128, n0 = pn * 128;

    int KT = K / 64;
    int tid = threadIdx.x;
    int wid = tid >> 5, lane = tid & 31;
    int wm = (wid & 3) * 32;
    int wn = (wid >> 2) * 64;
    int rl = lane >> 2, l3 = lane & 3;

    int arow = (wm + (lane & 15)) * HSTR + (lane >> 4) * 8;
    int brow = (wn + (lane & 7) + ((lane >> 4) << 3)) * HSTR + (((lane >> 3) & 1) << 3);

    auto loadAB = [&](int st, int kt){
        __half* sa = sh + st * (2*HTILE);
        __half* sb = sa + HTILE;
        int c = tid & 7;
        int r0 = tid >> 3;
        const __half* ga = A  + (long long)m0 * lda + kt * 64 + c * 8;
        const __half* gb = Bt + (long long)n0 * ldb + kt * 64 + c * 8;
        #pragma unroll
        for (int w = 0; w < 4; w++){
            int row = r0 + 32 * w;
            cp16(smem_u32(sa + row * HSTR + c * 8), ga + (long long)row * lda);
        }
        #pragma unroll
        for (int w = 0; w < 4; w++){
            int row = r0 + 32 * w;
            cp16(smem_u32(sb + row * HSTR + c * 8), gb + (long long)row * ldb);
        }
    };

    float acc[2][8][4];
    #pragma unroll
    for (int i=0;i<2;i++)
        #pragma unroll
        for (int j=0;j<8;j++)
            #pragma unroll
            for (int r=0;r<4;r++) acc[i][j][r] = 0.f;

    loadAB(0, 0); CP_COMMIT();
    if (KT > 1) loadAB(1, 1);
    CP_COMMIT();

    for (int kt = 0; kt < KT; kt++){
        int cur = kt % 3;
        CP_WAIT(1);
        __syncthreads();
        if (kt + 2 < KT) loadAB((kt + 2) % 3, kt + 2);
        CP_COMMIT();

        const __half* sa = sh + cur * (2*HTILE);
        const __half* sb = sa + HTILE;
        unsigned abase = smem_u32(sa) + arow * 2;
        unsigned bbase = smem_u32(sb) + brow * 2;
        #pragma unroll
        for (int ks = 0; ks < 4; ks++){
            unsigned koff = ks * 32;
            unsigned a[2][4];
            #pragma unroll
            for (int mi = 0; mi < 2; mi++)
                ldm_x4(a[mi][0], a[mi][1], a[mi][2], a[mi][3],
                       abase + mi * (16 * HSTR * 2) + koff);
            #pragma unroll
            for (int nip = 0; nip < 4; nip++){
                unsigned b0, b1, b2, b3;
                ldm_x4(b0, b1, b2, b3, bbase + nip * (16 * HSTR * 2) + koff);
                #pragma unroll
                for (int mi = 0; mi < 2; mi++){
                    mma_h(acc[mi][2*nip],   a[mi][0], a[mi][1], a[mi][2], a[mi][3], b0, b1);
                    mma_h(acc[mi][2*nip+1], a[mi][0], a[mi][1], a[mi][2], a[mi][3], b2, b3);
                }
            }
        }
    }

    int wsel = n0 >> 11;          // 0=q, 1=k, 2=v
    int n0l  = n0 & 2047;
    #pragma unroll
    for (int mi = 0; mi < 2; mi++){
        #pragma unroll
        for (int ni = 0; ni < 8; ni++){
            int row = m0 + wm + mi * 16 + rl;
            int col = n0l + wn + ni * 8 + l3 * 2;
            float v0 = acc[mi][ni][0];
            float v1 = acc[mi][ni][1];
            float v2 = acc[mi][ni][2];
            float v3 = acc[mi][ni][3];
            if (wsel < 2){
                int i = (col & 127) >> 1;
                float invf = g_invf[i];
                float a0 = (float)pos[row] * invf;
                float a1 = (float)pos[row + 8] * invf;
                float s0, c0, s1, c1;
                sincosf(a0, &s0, &c0);
                sincosf(a1, &s1, &c1);
                float t0 = v0 * c0 - v1 * s0;
                float t1 = v1 * c0 + v0 * s0;
                float t2 = v2 * c1 - v3 * s1;
                float t3 = v3 * c1 + v2 * s1;
                __half* O = wsel ? Kh : Qh;
                *(__half2*)(O + (long long)row * 2048 + col)       = __floats2half2_rn(t0, t1);
                *(__half2*)(O + (long long)(row + 8) * 2048 + col) = __floats2half2_rn(t2, t3);
            } else {
                int b = row >> 11, seq = row & 2047;
                int h = col >> 7,  dim = col & 127;
                __half* base = Vt + ((long long)(b * 16 + h) * 128) * 2048;
                base[(long long)dim * 2048 + seq]           = __float2half_rn(v0);
                base[(long long)(dim + 1) * 2048 + seq]     = __float2half_rn(v1);
                base[(long long)dim * 2048 + seq + 8]       = __float2half_rn(v2);
                base[(long long)(dim + 1) * 2048 + seq + 8] = __float2half_rn(v3);
            }
        }
    }
}

// ======== fused FFN (ldmatrix): g1h = fp16( silu(A@W1^T) * (A@W3^T) ) ========
#define FBTILE (64*HSTR)
#define FSTAGE (HTILE + 2*FBTILE)
#define SMEM_F (3*FSTAGE*2)              // 110592 B

__global__ void __launch_bounds__(256, 2)
gemm_ff(const __half* __restrict__ A, int lda,
        const __half* __restrict__ B1t, const __half* __restrict__ B3t, int ldb,
        __half* __restrict__ O, int ldo,
        int K, int npm, int npn)
{
    extern __shared__ __half sh[];

    int pid = blockIdx.x;
    const int GROUP = 16;
    int npg = GROUP * npn;
    int gid = pid / npg;
    int firstm = gid * GROUP;
    int gsz = min(GROUP, npm - firstm);
    int pm = firstm + (pid % npg) % gsz;
    int pn = (pid % npg) / gsz;
    int m0 = pm * 128, n0 = pn * 64;

    int KT = K / 64;
    int tid = threadIdx.x;
    int wid = tid >> 5, lane = tid & 31;
    int wm = (wid & 3) * 32;
    int wn = (wid >> 2) * 32;
    int rl = lane >> 2, l3 = lane & 3;

    int arow = (wm + (lane & 15)) * HSTR + (lane >> 4) * 8;
    int brow = (wn + (lane & 7) + ((lane >> 4) << 3)) * HSTR + (((lane >> 3) & 1) << 3);

    auto loadAB = [&](int st, int kt){
        __half* sa = sh + st * FSTAGE;
        __half* sb1 = sa + HTILE;
        __half* sb3 = sb1 + FBTILE;
        int c = tid & 7;
        int r0 = tid >> 3;
        const __half* ga = A + (long long)m0 * lda + kt * 64 + c * 8;
        #pragma unroll
        for (int w = 0; w < 4; w++){
            int row = r0 + 32 * w;
            cp16(smem_u32(sa + row * HSTR + c * 8), ga + (long long)row * lda);
        }
        const __half* g1 = B1t + (long long)n0 * ldb + kt * 64 + c * 8;
        const __half* g3 = B3t + (long long)n0 * ldb + kt * 64 + c * 8;
        #pragma unroll
        for (int w = 0; w < 2; w++){
            int row = r0 + 32 * w;
            cp16(smem_u32(sb1 + row * HSTR + c * 8), g1 + (long long)row * ldb);
        }
        #pragma unroll
        for (int w = 0; w < 2; w++){
            int row = r0 + 32 * w;
            cp16(smem_u32(sb3 + row * HSTR + c * 8), g3 + (long long)row * ldb);
        }
    };

    float ac1[2][4][4], ac3[2][4][4];
    #pragma unroll
    for (int i=0;i<2;i++)
        #pragma unroll
        for (int j=0;j<4;j++)
            #pragma unroll
            for (int r=0;r<4;r++){ ac1[i][j][r] = 0.f; ac3[i][j][r] = 0.f; }

    loadAB(0, 0); CP_COMMIT();
    if (KT > 1) loadAB(1, 1);
    CP_COMMIT();

    for (int kt = 0; kt < KT; kt++){
        int cur = kt % 3;
        CP_WAIT(1);
        __syncthreads();
        if (kt + 2 < KT) loadAB((kt + 2) % 3, kt + 2);
        CP_COMMIT();

        const __half* sa  = sh + cur * FSTAGE;
        const __half* sb1 = sa + HTILE;
        const __half* sb3 = sb1 + FBTILE;
        unsigned abase  = smem_u32(sa)  + arow * 2;
        unsigned b1base = smem_u32(sb1) + brow * 2;
        unsigned b3base = smem_u32(sb3) + brow * 2;
        #pragma unroll
        for (int ks = 0; ks < 4; ks++){
            unsigned koff = ks * 32;
            unsigned a[2][4];
            #pragma unroll
            for (int mi = 0; mi < 2; mi++)
                ldm_x4(a[mi][0], a[mi][1], a[mi][2], a[mi][3],
                       abase + mi * (16 * HSTR * 2) + koff);
            #pragma unroll
            for (int nip = 0; nip < 2; nip++){
                unsigned b0, b1, b2, b3;
                ldm_x4(b0, b1, b2, b3, b1base + nip * (16 * HSTR * 2) + koff);
                #pragma unroll
                for (int mi = 0; mi < 2; mi++){
                    mma_h(ac1[mi][2*nip],   a[mi][0], a[mi][1], a[mi][2], a[mi][3], b0, b1);
                    mma_h(ac1[mi][2*nip+1], a[mi][0], a[mi][1], a[mi][2], a[mi][3], b2, b3);
                }
                unsigned c0, c1, c2, c3;
                ldm_x4(c0, c1, c2, c3, b3base + nip * (16 * HSTR * 2) + koff);
                #pragma unroll
                for (int mi = 0; mi < 2; mi++){
                    mma_h(ac3[mi][2*nip],   a[mi][0], a[mi][1], a[mi][2], a[mi][3], c0, c1);
                    mma_h(ac3[mi][2*nip+1], a[mi][0], a[mi][1], a[mi][2], a[mi][3], c2, c3);
                }
            }
        }
    }

    #pragma unroll
    for (int mi = 0; mi < 2; mi++){
        #pragma unroll
        for (int ni = 0; ni < 4; ni++){
            int row = m0 + wm + mi * 16 + rl;
            int col = n0 + wn + ni * 8 + l3 * 2;
            float x0 = ac1[mi][ni][0], x1 = ac1[mi][ni][1];
            float x2 = ac1[mi][ni][2], x3 = ac1[mi][ni][3];
            float y0 = ac3[mi][ni][0], y1 = ac3[mi][ni][1];
            float y2 = ac3[mi][ni][2], y3 = ac3[mi][ni][3];
            float s0 = x0 / (1.0f + __expf(-x0)) * y0;
            float s1 = x1 / (1.0f + __expf(-x1)) * y1;
            float s2 = x2 / (1.0f + __expf(-x2)) * y2;
            float s3 = x3 / (1.0f + __expf(-x3)) * y3;
            *(__half2*)(O + (long long)row * ldo + col)       = __floats2half2_rn(s0, s1);
            *(__half2*)(O + (long long)(row + 8) * ldo + col) = __floats2half2_rn(s2, s3);
        }
    }
}

// ---------------- flash attention v3 (unchanged winner): fp16, 128-key tiles ------
#define FKSTR 136
#define FLASH_SMEM ((2*128*FKSTR + 2*128*FKSTR + 8*16*FKSTR)*2)

__global__ void __launch_bounds__(256, 1)
flash_h(const __half* __restrict__ Q, const __half* __restrict__ K,
        const __half* __restrict__ Vt, __half* __restrict__ O,
        float alpha)
{
    extern __shared__ __half sh[];
    __half* sKb  = sh;
    __half* sVtb = sh + 2*128*FKSTR;
    __half* sP   = sVtb + 2*128*FKSTR;

    int z = blockIdx.y;
    int b = z >> 4, h = z & 15;
    int qt = (gridDim.x - 1) - blockIdx.x;
    int q0 = qt * 128;
    const __half* Qg  = Q + ((long long)b * SEQ) * HIDDEN + h * HDIM;
    const __half* Kg  = K + ((long long)b * SEQ) * HIDDEN + h * HDIM;
    const __half* Vtg = Vt + ((long long)z * HDIM) * SEQ;
    __half* Og = O + ((long long)b * SEQ) * HIDDEN + h * HDIM;

    int tid = threadIdx.x, wid = tid >> 5, lane = tid & 31;
    int rl = lane >> 2, l3 = lane & 3;
    int qr = q0 + wid * 16;
    __half* sPw = sP + wid * 16 * FKSTR;

    unsigned qf[8][4];
    #pragma unroll
    for (int ks = 0; ks < 8; ks++){
        const __half* p0 = Qg + (long long)(qr + rl) * HIDDEN + ks * 16 + l3 * 2;
        const __half* p1 = Qg + (long long)(qr + rl + 8) * HIDDEN + ks * 16 + l3 * 2;
        qf[ks][0] = *(const unsigned*)(p0);
        qf[ks][1] = *(const unsigned*)(p1);
        qf[ks][2] = *(const unsigned*)(p0 + 8);
        qf[ks][3] = *(const unsigned*)(p1 + 8);
    }

    float Oa[16][4];
    #pragma unroll
    for (int ni = 0; ni < 16; ni++){
        Oa[ni][0] = 0.f; Oa[ni][1] = 0.f; Oa[ni][2] = 0.f; Oa[ni][3] = 0.f;
    }
    float m0r = -1e30f, m1r = -1e30f, l0r = 0.f, l1r = 0.f;

    auto loadKV = [&](int buf, int t){
        int c = tid & 15, r0 = tid >> 4;
        const __half* kp = Kg + (long long)(t * 128) * HIDDEN + c * 8;
        __half* dk = sKb + buf * 128 * FKSTR;
        #pragma unroll
        for (int w = 0; w < 8; w++){
            int row = r0 + 16 * w;
            cp16(smem_u32(dk + row * FKSTR + c * 8), kp + (long long)row * HIDDEN);
        }
        const __half* vp = Vtg + t * 128 + c * 8;
        __half* dv = sVtb + buf * 128 * FKSTR;
        #pragma unroll
        for (int w = 0; w < 8; w++){
            int row = r0 + 16 * w;
            cp16(smem_u32(dv + row * FKSTR + c * 8), vp + (long long)row * SEQ);
        }
    };

    int nt = qt + 1;
    loadKV(0, 0); CP_COMMIT();

    for (int t = 0; t < nt; t++){
        int buf = t & 1;
        if (t + 1 < nt){
            loadKV(buf ^ 1, t + 1);
            CP_COMMIT();
            CP_WAIT(1);
        } else {
            CP_WAIT(0);
        }
        __syncthreads();
        const __half* cK  = sKb  + buf * 128 * FKSTR;
        const __half* cVt = sVtb + buf * 128 * FKSTR;
        int diag = (t == qt);
        int k0 = t * 128;

        float Sa[16][4];
        #pragma unroll
        for (int ni = 0; ni < 16; ni++){
            Sa[ni][0]=0.f; Sa[ni][1]=0.f; Sa[ni][2]=0.f; Sa[ni][3]=0.f;
        }
        #pragma unroll
        for (int ks = 0; ks < 8; ks++){
            int kk = ks * 16;
            #pragma unroll
            for (int ni = 0; ni < 16; ni++){
                const __half* bp = cK + (ni * 8 + rl) * FKSTR + kk + l3 * 2;
                unsigned b0 = *(const unsigned*)(bp);
                unsigned b1 = *(const unsigned*)(bp + 8);
                mma_h(Sa[ni], qf[ks][0], qf[ks][1], qf[ks][2], qf[ks][3], b0, b1);
            }
        }

        int r0g = qr + rl, r1g = qr + rl + 8;
        float mx0 = -1e30f, mx1 = -1e30f;
        #pragma unroll
        for (int ni = 0; ni < 16; ni++){
            float x0 = Sa[ni][0] * alpha, x1 = Sa[ni][1] * alpha;
            float x2 = Sa[ni][2] * alpha, x3 = Sa[ni][3] * alpha;
            if (diag){
                int kg = k0 + ni * 8 + 2 * l3;
                if (kg     > r0g) x0 = -1e30f;
                if (kg + 1 > r0g) x1 = -1e30f;
                if (kg     > r1g) x2 = -1e30f;
                if (kg + 1 > r1g) x3 = -1e30f;
            }
            Sa[ni][0]=x0; Sa[ni][1]=x1; Sa[ni][2]=x2; Sa[ni][3]=x3;
            mx0 = fmaxf(mx0, fmaxf(x0, x1));
            mx1 = fmaxf(mx1, fmaxf(x2, x3));
        }
        mx0 = fmaxf(mx0, __shfl_xor_sync(0xffffffffu, mx0, 1));
        mx0 = fmaxf(mx0, __shfl_xor_sync(0xffffffffu, mx0, 2));
        mx1 = fmaxf(mx1, __shfl_xor_sync(0xffffffffu, mx1, 1));
        mx1 = fmaxf(mx1, __shfl_xor_sync(0xffffffffu, mx1, 2));

        float mn0 = fmaxf(m0r, mx0), mn1 = fmaxf(m1r, mx1);
        float cr0 = __expf(m0r - mn0), cr1 = __expf(m1r - mn1);
        m0r = mn0; m1r = mn1;
        l0r *= cr0; l1r *= cr1;
        #pragma unroll
        for (int ni = 0; ni < 16; ni++){
            Oa[ni][0] *= cr0; Oa[ni][1] *= cr0;
            Oa[ni][2] *= cr1; Oa[ni][3] *= cr1;
        }
        float rs0 = 0.f, rs1 = 0.f;
        #pragma unroll
        for (int ni = 0; ni < 16; ni++){
            float e0 = __expf(Sa[ni][0] - mn0);
            float e1 = __expf(Sa[ni][1] - mn0);
            float e2 = __expf(Sa[ni][2] - mn1);
            float e3 = __expf(Sa[ni][3] - mn1);
            rs0 += e0 + e1; rs1 += e2 + e3;
            int colp = ni * 8 + 2 * l3;
            *(__half2*)(sPw + rl * FKSTR + colp)       = __floats2half2_rn(e0, e1);
            *(__half2*)(sPw + (rl + 8) * FKSTR + colp) = __floats2half2_rn(e2, e3);
        }
        rs0 += __shfl_xor_sync(0xffffffffu, rs0, 1);
        rs0 += __shfl_xor_sync(0xffffffffu, rs0, 2);
        rs1 += __shfl_xor_sync(0xffffffffu, rs1, 1);
        rs1 += __shfl_xor_sync(0xffffffffu, rs1, 2);
        l0r += rs0; l1r += rs1;
        __syncwarp();

        #pragma unroll
        for (int ks = 0; ks < 8; ks++){
            int kk = ks * 16;
            const __half* ap0 = sPw + rl * FKSTR + kk + l3 * 2;
            const __half* ap1 = sPw + (rl + 8) * FKSTR + kk + l3 * 2;
            unsigned a0 = *(const unsigned*)(ap0);
            unsigned a1 = *(const unsigned*)(ap1);
            unsigned a2 = *(const unsigned*)(ap0 + 8);
            unsigned a3 = *(const unsigned*)(ap1 + 8);
            #pragma unroll
            for (int ni = 0; ni < 16; ni++){
                const __half* bp = cVt + (ni * 8 + rl) * FKSTR + kk + l3 * 2;
                unsigned b0 = *(const unsigned*)(bp);
                unsigned b1 = *(const unsigned*)(bp + 8);
                mma_h(Oa[ni], a0, a1, a2, a3, b0, b1);
            }
        }
        __syncthreads();
    }

    float inv0 = 1.0f / l0r, inv1 = 1.0f / l1r;
    #pragma unroll
    for (int ni = 0; ni < 16; ni++){
        int col = ni * 8 + 2 * l3;
        *(__half2*)(Og + (long long)(qr + rl) * HIDDEN + col) =
            __floats2half2_rn(Oa[ni][0] * inv0, Oa[ni][1] * inv0);
        *(__half2*)(Og + (long long)(qr + rl + 8) * HIDDEN + col) =
            __floats2half2_rn(Oa[ni][2] * inv1, Oa[ni][3] * inv1);
    }
}

// ---------------- transpose + fp16 ----------------
__global__ void transpose_h(const float* s0, __half* d0, const float* s1, __half* d1,
                            const float* s2, __half* d2, const float* s3, __half* d3,
                            int R, int C, int doInvf)
{
    __shared__ float t[32][33];
    const float* in; __half* out;
    switch (blockIdx.z){
        case 0:  in = s0; out = d0; break;
        case 1:  in = s1; out = d1; break;
        case 2:  in = s2; out = d2; break;
        default: in = s3; out = d3; break;
    }
    if (doInvf && blockIdx.x == 0 && blockIdx.y == 0 && blockIdx.z == 0){
        int f = threadIdx.y * 32 + threadIdx.x;
        if (f < 64) g_invf[f] = (float)exp(-(double)f * (log(500000.0) / 64.0));
    }
    int x  = blockIdx.x * 32 + threadIdx.x;
    int y0 = blockIdx.y * 32 + threadIdx.y;
    #pragma unroll
    for (int dy = 0; dy < 32; dy += 8)
        t[threadIdx.y + dy][threadIdx.x] = in[(long long)(y0 + dy) * C + x];
    __syncthreads();
    int ox  = blockIdx.y * 32 + threadIdx.x;
    int oy0 = blockIdx.x * 32 + threadIdx.y;
    #pragma unroll
    for (int dy = 0; dy < 32; dy += 8)
        out[(long long)(oy0 + dy) * R + ox] = __float2half_rn(t[threadIdx.x][threadIdx.y + dy]);
}

__global__ void rmsnorm_h(const float* __restrict__ X, const float* __restrict__ sc,
                          __half* __restrict__ O){
    long long base = (long long)blockIdx.x * HIDDEN;
    int tid = threadIdx.x;
    float v[8]; float ss = 0.f;
    #pragma unroll
    for (int i = 0; i < 8; i++){
        v[i] = X[base + tid + i * 256];
        ss += v[i] * v[i];
    }
    ss = blockReduceSum(ss);
    float r = rsqrtf(ss * (1.0f / (float)HIDDEN) + 1e-5f);
    #pragma unroll
    for (int i = 0; i < 8; i++){
        int c = tid + i * 256;
        O[base + c] = __float2half_rn(v[i] * r * sc[c]);
    }
}

// ---------------- launch ----------------
extern "C" void kernel_launch(void* const* d_in, const int* in_sizes, int n_in,
                              void* d_out, int out_size)
{
    const float* x   = (const float*)d_in[0];
    const int*   pos = (const int*)d_in[1];
    // d_in[2] = mask (causal; handled analytically)
    const float* wq  = (const float*)d_in[3];
    const float* wk  = (const float*)d_in[4];
    const float* wv  = (const float*)d_in[5];
    const float* wo  = (const float*)d_in[6];
    const float* asc = (const float*)d_in[7];
    const float* fsc = (const float*)d_in[8];
    const float* w1  = (const float*)d_in[9];
    const float* w3  = (const float*)d_in[10];
    const float* w2  = (const float*)d_in[11];
    float* out = (float*)d_out;

    __half *p_xnh,*p_qh,*p_kh,*p_vth,*p_aoh,*p_ffnh,*p_g1h;
    float *p_h;
    __half *p_wqkv,*p_wo,*p_w1,*p_w3,*p_w2;
    cudaGetSymbolAddress((void**)&p_xnh,  g_xnh);
    cudaGetSymbolAddress((void**)&p_qh,   g_qh);
    cudaGetSymbolAddress((void**)&p_kh,   g_kh);
    cudaGetSymbolAddress((void**)&p_vth,  g_vth);
    cudaGetSymbolAddress((void**)&p_aoh,  g_aoh);
    cudaGetSymbolAddress((void**)&p_h,    g_h);
    cudaGetSymbolAddress((void**)&p_ffnh, g_ffnh);
    cudaGetSymbolAddress((void**)&p_g1h,  g_g1h);
    cudaGetSymbolAddress((void**)&p_wqkv, g_wqkv);
    cudaGetSymbolAddress((void**)&p_wo,   g_wo);
    cudaGetSymbolAddress((void**)&p_w1,   g_w1);
    cudaGetSymbolAddress((void**)&p_w3,   g_w3);
    cudaGetSymbolAddress((void**)&p_w2,   g_w2);

    cudaFuncSetAttribute(gemm_h,   cudaFuncAttributeMaxDynamicSharedMemorySize, SMEM_H);
    cudaFuncSetAttribute(gemm_qkv, cudaFuncAttributeMaxDynamicSharedMemorySize, SMEM_H);
    cudaFuncSetAttribute(gemm_ff,  cudaFuncAttributeMaxDynamicSharedMemorySize, SMEM_F);
    cudaFuncSetAttribute(flash_h,  cudaFuncAttributeMaxDynamicSharedMemorySize, FLASH_SMEM);

    // 0. transpose + fp16 weights; wq|wk|wv concatenated into wqkv
    transpose_h<<<dim3(64,64,4), dim3(32,8)>>>(
        wq, p_wqkv,
        wk, p_wqkv + (size_t)HIDDEN*HIDDEN,
        wv, p_wqkv + (size_t)2*HIDDEN*HIDDEN,
        wo, p_wo, HIDDEN, HIDDEN, 1);
    transpose_h<<<dim3(176,64,2), dim3(32,8)>>>(w1,p_w1, w3,p_w3, nullptr,nullptr,
                                                nullptr,nullptr, HIDDEN, FFDIM, 0);
    transpose_h<<<dim3(64,176,1), dim3(32,8)>>>(w2,p_w2, nullptr,nullptr, nullptr,nullptr,
                                                nullptr,nullptr, FFDIM, HIDDEN, 0);

    // 1. rmsnorm (attn) -> fp16
    rmsnorm_h<<<NTOK,256>>>(x, asc, p_xnh);

    // 2. merged QKV projection (N=6144), rope->fp16 q/k, transposed fp16 v
    dim3 gQKV(32*48, 1, 1);
    gemm_qkv<<<gQKV,256,SMEM_H>>>(p_xnh,HIDDEN, p_wqkv,HIDDEN,
                                  p_qh, p_kh, p_vth, pos, HIDDEN, 32,48);

    // 3. flash attention (fp16)
    flash_h<<<dim3(16, BATCHN*NHEADS),256,FLASH_SMEM>>>(
        p_qh, p_kh, p_vth, p_aoh, 0.08838834764831845f);

    // 4. h = x + attn_out @ wo
    dim3 gProj(32*16, 1, 1);
    gemm_h<<<gProj,256,SMEM_H>>>(p_aoh,HIDDEN, p_wo,HIDDEN, p_h,HIDDEN,
                                 x, HIDDEN, 32,16);

    // 5. rmsnorm (ffn) -> fp16
    rmsnorm_h<<<NTOK,256>>>(p_h, fsc, p_ffnh);

    // 6. fused FFN up+gate+silu -> g1h
    dim3 gFF(32*88, 1, 1);
    gemm_ff<<<gFF,256,SMEM_F>>>(p_ffnh,HIDDEN, p_w1,p_w3,HIDDEN, p_g1h,FFDIM,
                                HIDDEN, 32,88);

    // 7. out = h + g1h @ w2  (K = 5632)
    gemm_h<<<gProj,256,SMEM_H>>>(p_g1h,FFDIM, p_w2,FFDIM, out,HIDDEN,
                                 p_h, FFDIM, 32,16);
}

// round 12
// speedup vs baseline: 2.0772x; 1.0026x over previous
#include <cuda_runtime.h>
#include <cuda_fp16.h>
#include <cstdint>
#include <math.h>

#define HIDDEN 2048
#define NHEADS 16
#define HDIM 128
#define FFDIM 5632
#define BATCHN 2
#define SEQ 2048
#define NTOK (BATCHN*SEQ)   // 4096

// ---------------- scratch ----------------
__device__ __half g_xnh[NTOK*HIDDEN];
__device__ __half g_qh[NTOK*HIDDEN];
__device__ __half g_kh[NTOK*HIDDEN];
__device__ __half g_vth[BATCHN*NHEADS*HDIM*SEQ];   // V transposed: [b,h,dim,seq]
__device__ __half g_aoh[NTOK*HIDDEN];
__device__ float  g_h[NTOK*HIDDEN];
__device__ __half g_ffnh[NTOK*HIDDEN];
__device__ __half g_g1h[(size_t)NTOK*FFDIM];
__device__ float  g_invf[64];
// fp16 TRANSPOSED weights [N, K] K-major
__device__ __half g_wqkv[3*HIDDEN*HIDDEN];         // wq | wk | wv concatenated
__device__ __half g_wo[HIDDEN*HIDDEN];
__device__ __half g_w1[(size_t)HIDDEN*FFDIM];
__device__ __half g_w3[(size_t)HIDDEN*FFDIM];
__device__ __half g_w2[(size_t)FFDIM*HIDDEN];

// ---------------- helpers ----------------
__device__ __forceinline__ unsigned smem_u32(const void* p){
    return (unsigned)__cvta_generic_to_shared(p);
}
__device__ __forceinline__ void cp16(unsigned s, const void* g){
    asm volatile("cp.async.cg.shared.global [%0], [%1], 16;\n" :: "r"(s), "l"(g));
}
#define CP_COMMIT() asm volatile("cp.async.commit_group;\n")
#define CP_WAIT(n)  asm volatile("cp.async.wait_group %0;\n" :: "n"(n))

__device__ __forceinline__ void mma_h(float c[4],
        unsigned a0, unsigned a1, unsigned a2, unsigned a3,
        unsigned b0, unsigned b1){
    asm volatile("mma.sync.aligned.m16n8k16.row.col.f32.f16.f16.f32 "
        "{%0,%1,%2,%3},{%4,%5,%6,%7},{%8,%9},{%0,%1,%2,%3};\n"
        : "+f"(c[0]), "+f"(c[1]), "+f"(c[2]), "+f"(c[3])
        : "r"(a0), "r"(a1), "r"(a2), "r"(a3), "r"(b0), "r"(b1));
}
__device__ __forceinline__ void ldm_x4(unsigned &r0, unsigned &r1, unsigned &r2, unsigned &r3,
                                       unsigned addr){
    asm volatile("ldmatrix.sync.aligned.m8n8.x4.shared.b16 {%0,%1,%2,%3}, [%4];"
        : "=r"(r0), "=r"(r1), "=r"(r2), "=r"(r3) : "r"(addr));
}

__device__ __forceinline__ float warpReduceSum(float v){
    #pragma unroll
    for (int o=16;o;o>>=1) v += __shfl_xor_sync(0xffffffffu, v, o);
    return v;
}
__device__ float blockReduceSum(float v){   // 256 threads
    __shared__ float s[8]; __shared__ float tot;
    int lane = threadIdx.x & 31, w = threadIdx.x >> 5;
    v = warpReduceSum(v);
    if (!lane) s[w] = v;
    __syncthreads();
    if (w == 0){
        float t = (lane < 8) ? s[lane] : 0.f;
        t = warpReduceSum(t);
        if (!lane) tot = t;
    }
    __syncthreads();
    return tot;
}

// ======== fp16 GEMM (3-stage pipeline + ldmatrix): C[M,N](f32) = A @ Bt^T (+ Res) ==
#define HSTR 72
#define HTILE (128*HSTR)
#define SMEM_H (3*2*HTILE*2)             // 110592 B

__global__ void __launch_bounds__(256, 2)
gemm_h(const __half* __restrict__ A, int lda,
       const __half* __restrict__ Bt, int ldb,
       float* __restrict__ C, int ldc,
       const float* __restrict__ Res,
       int K, int npm, int npn)
{
    extern __shared__ __half sh[];

    int pid = blockIdx.x;
    const int GROUP = 16;
    int npg = GROUP * npn;
    int gid = pid / npg;
    int firstm = gid * GROUP;
    int gsz = min(GROUP, npm - firstm);
    int pm = firstm + (pid % npg) % gsz;
    int pn = (pid % npg) / gsz;
    int m0 = pm * 128, n0 = pn * 128;

    int KT = K / 64;
    int tid = threadIdx.x;
    int wid = tid >> 5, lane = tid & 31;
    int wm = (wid & 3) * 32;
    int wn = (wid >> 2) * 64;
    int rl = lane >> 2, l3 = lane & 3;

    int arow = (wm + (lane & 15)) * HSTR + (lane >> 4) * 8;
    int brow = (wn + (lane & 7) + ((lane >> 4) << 3)) * HSTR + (((lane >> 3) & 1) << 3);

    auto loadAB = [&](int st, int kt){
        __half* sa = sh + st * (2*HTILE);
        __half* sb = sa + HTILE;
        int c = tid & 7;
        int r0 = tid >> 3;
        const __half* ga = A  + (long long)m0 * lda + kt * 64 + c * 8;
        const __half* gb = Bt + (long long)n0 * ldb + kt * 64 + c * 8;
        #pragma unroll
        for (int w = 0; w < 4; w++){
            int row = r0 + 32 * w;
            cp16(smem_u32(sa + row * HSTR + c * 8), ga + (long long)row * lda);
        }
        #pragma unroll
        for (int w = 0; w < 4; w++){
            int row = r0 + 32 * w;
            cp16(smem_u32(sb + row * HSTR + c * 8), gb + (long long)row * ldb);
        }
    };

    float acc[2][8][4];
    #pragma unroll
    for (int i=0;i<2;i++)
        #pragma unroll
        for (int j=0;j<8;j++)
            #pragma unroll
            for (int r=0;r<4;r++) acc[i][j][r] = 0.f;

    loadAB(0, 0); CP_COMMIT();
    if (KT > 1) loadAB(1, 1);
    CP_COMMIT();

    for (int kt = 0; kt < KT; kt++){
        int cur = kt % 3;
        CP_WAIT(1);
        __syncthreads();
        if (kt + 2 < KT) loadAB((kt + 2) % 3, kt + 2);
        CP_COMMIT();

        const __half* sa = sh + cur * (2*HTILE);
        const __half* sb = sa + HTILE;
        unsigned abase = smem_u32(sa) + arow * 2;
        unsigned bbase = smem_u32(sb) + brow * 2;
        #pragma unroll
        for (int ks = 0; ks < 4; ks++){
            unsigned koff = ks * 32;
            unsigned a[2][4];
            #pragma unroll
            for (int mi = 0; mi < 2; mi++)
                ldm_x4(a[mi][0], a[mi][1], a[mi][2], a[mi][3],
                       abase + mi * (16 * HSTR * 2) + koff);
            #pragma unroll
            for (int nip = 0; nip < 4; nip++){
                unsigned b0, b1, b2, b3;
                ldm_x4(b0, b1, b2, b3, bbase + nip * (16 * HSTR * 2) + koff);
                #pragma unroll
                for (int mi = 0; mi < 2; mi++){
                    mma_h(acc[mi][2*nip],   a[mi][0], a[mi][1], a[mi][2], a[mi][3], b0, b1);
                    mma_h(acc[mi][2*nip+1], a[mi][0], a[mi][1], a[mi][2], a[mi][3], b2, b3);
                }
            }
        }
    }

    #pragma unroll
    for (int mi = 0; mi < 2; mi++){
        #pragma unroll
        for (int ni = 0; ni < 8; ni++){
            int row = m0 + wm + mi * 16 + rl;
            int col = n0 + wn + ni * 8 + l3 * 2;
            float v0 = acc[mi][ni][0];
            float v1 = acc[mi][ni][1];
            float v2 = acc[mi][ni][2];
            float v3 = acc[mi][ni][3];
            if (Res){
                float2 r01 = *(const float2*)(Res + (long long)row * ldc + col);
                float2 r23 = *(const float2*)(Res + (long long)(row + 8) * ldc + col);
                v0 += r01.x; v1 += r01.y; v2 += r23.x; v3 += r23.y;
            }
            *(float2*)(C + (long long)row * ldc + col)       = make_float2(v0, v1);
            *(float2*)(C + (long long)(row + 8) * ldc + col) = make_float2(v2, v3);
        }
    }
}

// ======== merged QKV gemm (ldmatrix): N=6144; epilogue rope->fp16 / V-transpose ===
__global__ void __launch_bounds__(256, 2)
gemm_qkv(const __half* __restrict__ A, int lda,
         const __half* __restrict__ Bt, int ldb,
         __half* __restrict__ Qh, __half* __restrict__ Kh, __half* __restrict__ Vt,
         const int* __restrict__ pos, int K, int npm, int npn)
{
    extern __shared__ __half sh[];

    int pid = blockIdx.x;
    const int GROUP = 16;
    int npg = GROUP * npn;
    int gid = pid / npg;
    int firstm = gid * GROUP;
    int gsz = min(GROUP, npm - firstm);
    int pm = firstm + (pid % npg) % gsz;
    int pn = (pid % npg) / gsz;
    int m0 = pm * 128, n0 = pn * 128;

    int KT = K / 64;
    int tid = threadIdx.x;
    int wid = tid >> 5, lane = tid & 31;
    int wm = (wid & 3) * 32;
    int wn = (wid >> 2) * 64;
    int rl = lane >> 2, l3 = lane & 3;

    int arow = (wm + (lane & 15)) * HSTR + (lane >> 4) * 8;
    int brow = (wn + (lane & 7) + ((lane >> 4) << 3)) * HSTR + (((lane >> 3) & 1) << 3);

    auto loadAB = [&](int st, int kt){
        __half* sa = sh + st * (2*HTILE);
        __half* sb = sa + HTILE;
        int c = tid & 7;
        int r0 = tid >> 3;
        const __half* ga = A  + (long long)m0 * lda + kt * 64 + c * 8;
        const __half* gb = Bt + (long long)n0 * ldb + kt * 64 + c * 8;
        #pragma unroll
        for (int w = 0; w < 4; w++){
            int row = r0 + 32 * w;
            cp16(smem_u32(sa + row * HSTR + c * 8), ga + (long long)row * lda);
        }
        #pragma unroll
        for (int w = 0; w < 4; w++){
            int row = r0 + 32 * w;
            cp16(smem_u32(sb + row * HSTR + c * 8), gb + (long long)row * ldb);
        }
    };

    float acc[2][8][4];
    #pragma unroll
    for (int i=0;i<2;i++)
        #pragma unroll
        for (int j=0;j<8;j++)
            #pragma unroll
            for (int r=0;r<4;r++) acc[i][j][r] = 0.f;

    loadAB(0, 0); CP_COMMIT();
    if (KT > 1) loadAB(1, 1);
    CP_COMMIT();

    for (int kt = 0; kt < KT; kt++){
        int cur = kt % 3;
        CP_WAIT(1);
        __syncthreads();
        if (kt + 2 < KT) loadAB((kt + 2) % 3, kt + 2);
        CP_COMMIT();

        const __half* sa = sh + cur * (2*HTILE);
        const __half* sb = sa + HTILE;
        unsigned abase = smem_u32(sa) + arow * 2;
        unsigned bbase = smem_u32(sb) + brow * 2;
        #pragma unroll
        for (int ks = 0; ks < 4; ks++){
            unsigned koff = ks * 32;
            unsigned a[2][4];
            #pragma unroll
            for (int mi = 0; mi < 2; mi++)
                ldm_x4(a[mi][0], a[mi][1], a[mi][2], a[mi][3],
                       abase + mi * (16 * HSTR * 2) + koff);
            #pragma unroll
            for (int nip = 0; nip < 4; nip++){
                unsigned b0, b1, b2, b3;
                ldm_x4(b0, b1, b2, b3, bbase + nip * (16 * HSTR * 2) + koff);
                #pragma unroll
                for (int mi = 0; mi < 2; mi++){
                    mma_h(acc[mi][2*nip],   a[mi][0], a[mi][1], a[mi][2], a[mi][3], b0, b1);
                    mma_h(acc[mi][2*nip+1], a[mi][0], a[mi][1], a[mi][2], a[mi][3], b2, b3);
                }
            }
        }
    }

    int wsel = n0 >> 11;          // 0=q, 1=k, 2=v
    int n0l  = n0 & 2047;
    #pragma unroll
    for (int mi = 0; mi < 2; mi++){
        #pragma unroll
        for (int ni = 0; ni < 8; ni++){
            int row = m0 + wm + mi * 16 + rl;
            int col = n0l + wn + ni * 8 + l3 * 2;
            float v0 = acc[mi][ni][0];
            float v1 = acc[mi][ni][1];
            float v2 = acc[mi][ni][2];
            float v3 = acc[mi][ni][3];
            if (wsel < 2){
                int i = (col & 127) >> 1;
                float invf = g_invf[i];
                float a0 = (float)pos[row] * invf;
                float a1 = (float)pos[row + 8] * invf;
                float s0, c0, s1, c1;
                sincosf(a0, &s0, &c0);
                sincosf(a1, &s1, &c1);
                float t0 = v0 * c0 - v1 * s0;
                float t1 = v1 * c0 + v0 * s0;
                float t2 = v2 * c1 - v3 * s1;
                float t3 = v3 * c1 + v2 * s1;
                __half* O = wsel ? Kh : Qh;
                *(__half2*)(O + (long long)row * 2048 + col)       = __floats2half2_rn(t0, t1);
                *(__half2*)(O + (long long)(row + 8) * 2048 + col) = __floats2half2_rn(t2, t3);
            } else {
                int b = row >> 11, seq = row & 2047;
                int h = col >> 7,  dim = col & 127;
                __half* base = Vt + ((long long)(b * 16 + h) * 128) * 2048;
                base[(long long)dim * 2048 + seq]           = __float2half_rn(v0);
                base[(long long)(dim + 1) * 2048 + seq]     = __float2half_rn(v1);
                base[(long long)dim * 2048 + seq + 8]       = __float2half_rn(v2);
                base[(long long)(dim + 1) * 2048 + seq + 8] = __float2half_rn(v3);
            }
        }
    }
}

// ======== fused FFN (ldmatrix): g1h = fp16( silu(A@W1^T) * (A@W3^T) ) ========
#define FBTILE (64*HSTR)
#define FSTAGE (HTILE + 2*FBTILE)
#define SMEM_F (3*FSTAGE*2)              // 110592 B

__global__ void __launch_bounds__(256, 2)
gemm_ff(const __half* __restrict__ A, int lda,
        const __half* __restrict__ B1t, const __half* __restrict__ B3t, int ldb,
        __half* __restrict__ O, int ldo,
        int K, int npm, int npn)
{
    extern __shared__ __half sh[];

    int pid = blockIdx.x;
    const int GROUP = 16;
    int npg = GROUP * npn;
    int gid = pid / npg;
    int firstm = gid * GROUP;
    int gsz = min(GROUP, npm - firstm);
    int pm = firstm + (pid % npg) % gsz;
    int pn = (pid % npg) / gsz;
    int m0 = pm * 128, n0 = pn * 64;

    int KT = K / 64;
    int tid = threadIdx.x;
    int wid = tid >> 5, lane = tid & 31;
    int wm = (wid & 3) * 32;
    int wn = (wid >> 2) * 32;
    int rl = lane >> 2, l3 = lane & 3;

    int arow = (wm + (lane & 15)) * HSTR + (lane >> 4) * 8;
    int brow = (wn + (lane & 7) + ((lane >> 4) << 3)) * HSTR + (((lane >> 3) & 1) << 3);

    auto loadAB = [&](int st, int kt){
        __half* sa = sh + st * FSTAGE;
        __half* sb1 = sa + HTILE;
        __half* sb3 = sb1 + FBTILE;
        int c = tid & 7;
        int r0 = tid >> 3;
        const __half* ga = A + (long long)m0 * lda + kt * 64 + c * 8;
        #pragma unroll
        for (int w = 0; w < 4; w++){
            int row = r0 + 32 * w;
            cp16(smem_u32(sa + row * HSTR + c * 8), ga + (long long)row * lda);
        }
        const __half* g1 = B1t + (long long)n0 * ldb + kt * 64 + c * 8;
        const __half* g3 = B3t + (long long)n0 * ldb + kt * 64 + c * 8;
        #pragma unroll
        for (int w = 0; w < 2; w++){
            int row = r0 + 32 * w;
            cp16(smem_u32(sb1 + row * HSTR + c * 8), g1 + (long long)row * ldb);
        }
        #pragma unroll
        for (int w = 0; w < 2; w++){
            int row = r0 + 32 * w;
            cp16(smem_u32(sb3 + row * HSTR + c * 8), g3 + (long long)row * ldb);
        }
    };

    float ac1[2][4][4], ac3[2][4][4];
    #pragma unroll
    for (int i=0;i<2;i++)
        #pragma unroll
        for (int j=0;j<4;j++)
            #pragma unroll
            for (int r=0;r<4;r++){ ac1[i][j][r] = 0.f; ac3[i][j][r] = 0.f; }

    loadAB(0, 0); CP_COMMIT();
    if (KT > 1) loadAB(1, 1);
    CP_COMMIT();

    for (int kt = 0; kt < KT; kt++){
        int cur = kt % 3;
        CP_WAIT(1);
        __syncthreads();
        if (kt + 2 < KT) loadAB((kt + 2) % 3, kt + 2);
        CP_COMMIT();

        const __half* sa  = sh + cur * FSTAGE;
        const __half* sb1 = sa + HTILE;
        const __half* sb3 = sb1 + FBTILE;
        unsigned abase  = smem_u32(sa)  + arow * 2;
        unsigned b1base = smem_u32(sb1) + brow * 2;
        unsigned b3base = smem_u32(sb3) + brow * 2;
        #pragma unroll
        for (int ks = 0; ks < 4; ks++){
            unsigned koff = ks * 32;
            unsigned a[2][4];
            #pragma unroll
            for (int mi = 0; mi < 2; mi++)
                ldm_x4(a[mi][0], a[mi][1], a[mi][2], a[mi][3],
                       abase + mi * (16 * HSTR * 2) + koff);
            #pragma unroll
            for (int nip = 0; nip < 2; nip++){
                unsigned b0, b1, b2, b3;
                ldm_x4(b0, b1, b2, b3, b1base + nip * (16 * HSTR * 2) + koff);
                #pragma unroll
                for (int mi = 0; mi < 2; mi++){
                    mma_h(ac1[mi][2*nip],   a[mi][0], a[mi][1], a[mi][2], a[mi][3], b0, b1);
                    mma_h(ac1[mi][2*nip+1], a[mi][0], a[mi][1], a[mi][2], a[mi][3], b2, b3);
                }
                unsigned c0, c1, c2, c3;
                ldm_x4(c0, c1, c2, c3, b3base + nip * (16 * HSTR * 2) + koff);
                #pragma unroll
                for (int mi = 0; mi < 2; mi++){
                    mma_h(ac3[mi][2*nip],   a[mi][0], a[mi][1], a[mi][2], a[mi][3], c0, c1);
                    mma_h(ac3[mi][2*nip+1], a[mi][0], a[mi][1], a[mi][2], a[mi][3], c2, c3);
                }
            }
        }
    }

    #pragma unroll
    for (int mi = 0; mi < 2; mi++){
        #pragma unroll
        for (int ni = 0; ni < 4; ni++){
            int row = m0 + wm + mi * 16 + rl;
            int col = n0 + wn + ni * 8 + l3 * 2;
            float x0 = ac1[mi][ni][0], x1 = ac1[mi][ni][1];
            float x2 = ac1[mi][ni][2], x3 = ac1[mi][ni][3];
            float y0 = ac3[mi][ni][0], y1 = ac3[mi][ni][1];
            float y2 = ac3[mi][ni][2], y3 = ac3[mi][ni][3];
            float s0 = x0 / (1.0f + __expf(-x0)) * y0;
            float s1 = x1 / (1.0f + __expf(-x1)) * y1;
            float s2 = x2 / (1.0f + __expf(-x2)) * y2;
            float s3 = x3 / (1.0f + __expf(-x3)) * y3;
            *(__half2*)(O + (long long)row * ldo + col)       = __floats2half2_rn(s0, s1);
            *(__half2*)(O + (long long)(row + 8) * ldo + col) = __floats2half2_rn(s2, s3);
        }
    }
}

// ---------------- flash attention v4: fp16, 128-key tiles, ldmatrix ----------------
#define FKSTR 136
#define FLASH_SMEM ((2*128*FKSTR + 2*128*FKSTR + 8*16*FKSTR)*2)

__global__ void __launch_bounds__(256, 1)
flash_h(const __half* __restrict__ Q, const __half* __restrict__ K,
        const __half* __restrict__ Vt, __half* __restrict__ O,
        float alpha)
{
    extern __shared__ __half sh[];
    __half* sKb  = sh;
    __half* sVtb = sh + 2*128*FKSTR;
    __half* sP   = sVtb + 2*128*FKSTR;

    int z = blockIdx.y;
    int b = z >> 4, h = z & 15;
    int qt = (gridDim.x - 1) - blockIdx.x;
    int q0 = qt * 128;
    const __half* Qg  = Q + ((long long)b * SEQ) * HIDDEN + h * HDIM;
    const __half* Kg  = K + ((long long)b * SEQ) * HIDDEN + h * HDIM;
    const __half* Vtg = Vt + ((long long)z * HDIM) * SEQ;
    __half* Og = O + ((long long)b * SEQ) * HIDDEN + h * HDIM;

    int tid = threadIdx.x, wid = tid >> 5, lane = tid & 31;
    int rl = lane >> 2, l3 = lane & 3;
    int qr = q0 + wid * 16;
    __half* sPw = sP + wid * 16 * FKSTR;

    // ldmatrix per-lane row offsets (in halves) within a 128-row smem block
    int brow = ((lane & 7) + ((lane >> 4) << 3)) * FKSTR + (((lane >> 3) & 1) << 3);
    int parow = (lane & 15) * FKSTR + ((lane >> 4) << 3);   // within this warp's sP region

    unsigned qf[8][4];
    #pragma unroll
    for (int ks = 0; ks < 8; ks++){
        const __half* p0 = Qg + (long long)(qr + rl) * HIDDEN + ks * 16 + l3 * 2;
        const __half* p1 = Qg + (long long)(qr + rl + 8) * HIDDEN + ks * 16 + l3 * 2;
        qf[ks][0] = *(const unsigned*)(p0);
        qf[ks][1] = *(const unsigned*)(p1);
        qf[ks][2] = *(const unsigned*)(p0 + 8);
        qf[ks][3] = *(const unsigned*)(p1 + 8);
    }

    float Oa[16][4];
    #pragma unroll
    for (int ni = 0; ni < 16; ni++){
        Oa[ni][0] = 0.f; Oa[ni][1] = 0.f; Oa[ni][2] = 0.f; Oa[ni][3] = 0.f;
    }
    float m0r = -1e30f, m1r = -1e30f, l0r = 0.f, l1r = 0.f;

    auto loadKV = [&](int buf, int t){
        int c = tid & 15, r0 = tid >> 4;
        const __half* kp = Kg + (long long)(t * 128) * HIDDEN + c * 8;
        __half* dk = sKb + buf * 128 * FKSTR;
        #pragma unroll
        for (int w = 0; w < 8; w++){
            int row = r0 + 16 * w;
            cp16(smem_u32(dk + row * FKSTR + c * 8), kp + (long long)row * HIDDEN);
        }
        const __half* vp = Vtg + t * 128 + c * 8;
        __half* dv = sVtb + buf * 128 * FKSTR;
        #pragma unroll
        for (int w = 0; w < 8; w++){
            int row = r0 + 16 * w;
            cp16(smem_u32(dv + row * FKSTR + c * 8), vp + (long long)row * SEQ);
        }
    };

    int nt = qt + 1;
    loadKV(0, 0); CP_COMMIT();

    for (int t = 0; t < nt; t++){
        int buf = t & 1;
        if (t + 1 < nt){
            loadKV(buf ^ 1, t + 1);
            CP_COMMIT();
            CP_WAIT(1);
        } else {
            CP_WAIT(0);
        }
        __syncthreads();
        const __half* cK  = sKb  + buf * 128 * FKSTR;
        const __half* cVt = sVtb + buf * 128 * FKSTR;
        unsigned kbase = smem_u32(cK)  + brow * 2;
        unsigned vbase = smem_u32(cVt) + brow * 2;
        int diag = (t == qt);
        int k0 = t * 128;

        // S = Q @ K^T over 128 keys (8 n-frag pairs via ldmatrix x4)
        float Sa[16][4];
        #pragma unroll
        for (int ni = 0; ni < 16; ni++){
            Sa[ni][0]=0.f; Sa[ni][1]=0.f; Sa[ni][2]=0.f; Sa[ni][3]=0.f;
        }
        #pragma unroll
        for (int ks = 0; ks < 8; ks++){
            unsigned koff = ks * 32;
            #pragma unroll
            for (int nip = 0; nip < 8; nip++){
                unsigned b0, b1, b2, b3;
                ldm_x4(b0, b1, b2, b3, kbase + nip * (16 * FKSTR * 2) + koff);
                mma_h(Sa[2*nip],   qf[ks][0], qf[ks][1], qf[ks][2], qf[ks][3], b0, b1);
                mma_h(Sa[2*nip+1], qf[ks][0], qf[ks][1], qf[ks][2], qf[ks][3], b2, b3);
            }
        }

        int r0g = qr + rl, r1g = qr + rl + 8;
        float mx0 = -1e30f, mx1 = -1e30f;
        #pragma unroll
        for (int ni = 0; ni < 16; ni++){
            float x0 = Sa[ni][0] * alpha, x1 = Sa[ni][1] * alpha;
            float x2 = Sa[ni][2] * alpha, x3 = Sa[ni][3] * alpha;
            if (diag){
                int kg = k0 + ni * 8 + 2 * l3;
                if (kg     > r0g) x0 = -1e30f;
                if (kg + 1 > r0g) x1 = -1e30f;
                if (kg     > r1g) x2 = -1e30f;
                if (kg + 1 > r1g) x3 = -1e30f;
            }
            Sa[ni][0]=x0; Sa[ni][1]=x1; Sa[ni][2]=x2; Sa[ni][3]=x3;
            mx0 = fmaxf(mx0, fmaxf(x0, x1));
            mx1 = fmaxf(mx1, fmaxf(x2, x3));
        }
        mx0 = fmaxf(mx0, __shfl_xor_sync(0xffffffffu, mx0, 1));
        mx0 = fmaxf(mx0, __shfl_xor_sync(0xffffffffu, mx0, 2));
        mx1 = fmaxf(mx1, __shfl_xor_sync(0xffffffffu, mx1, 1));
        mx1 = fmaxf(mx1, __shfl_xor_sync(0xffffffffu, mx1, 2));

        float mn0 = fmaxf(m0r, mx0), mn1 = fmaxf(m1r, mx1);
        float cr0 = __expf(m0r - mn0), cr1 = __expf(m1r - mn1);
        m0r = mn0; m1r = mn1;
        l0r *= cr0; l1r *= cr1;
        #pragma unroll
        for (int ni = 0; ni < 16; ni++){
            Oa[ni][0] *= cr0; Oa[ni][1] *= cr0;
            Oa[ni][2] *= cr1; Oa[ni][3] *= cr1;
        }
        float rs0 = 0.f, rs1 = 0.f;
        #pragma unroll
        for (int ni = 0; ni < 16; ni++){
            float e0 = __expf(Sa[ni][0] - mn0);
            float e1 = __expf(Sa[ni][1] - mn0);
            float e2 = __expf(Sa[ni][2] - mn1);
            float e3 = __expf(Sa[ni][3] - mn1);
            rs0 += e0 + e1; rs1 += e2 + e3;
            int colp = ni * 8 + 2 * l3;
            *(__half2*)(sPw + rl * FKSTR + colp)       = __floats2half2_rn(e0, e1);
            *(__half2*)(sPw + (rl + 8) * FKSTR + colp) = __floats2half2_rn(e2, e3);
        }
        rs0 += __shfl_xor_sync(0xffffffffu, rs0, 1);
        rs0 += __shfl_xor_sync(0xffffffffu, rs0, 2);
        rs1 += __shfl_xor_sync(0xffffffffu, rs1, 1);
        rs1 += __shfl_xor_sync(0xffffffffu, rs1, 2);
        l0r += rs0; l1r += rs1;
        __syncwarp();

        // O += P @ V (ldmatrix for P A-frags and Vt B-frags)
        unsigned pbase = smem_u32(sPw) + parow * 2;
        #pragma unroll
        for (int ks = 0; ks < 8; ks++){
            unsigned koff = ks * 32;
            unsigned a0, a1, a2, a3;
            ldm_x4(a0, a1, a2, a3, pbase + koff);
            #pragma unroll
            for (int nip = 0; nip < 8; nip++){
                unsigned b0, b1, b2, b3;
                ldm_x4(b0, b1, b2, b3, vbase + nip * (16 * FKSTR * 2) + koff);
                mma_h(Oa[2*nip],   a0, a1, a2, a3, b0, b1);
                mma_h(Oa[2*nip+1], a0, a1, a2, a3, b2, b3);
            }
        }
        __syncthreads();
    }

    float inv0 = 1.0f / l0r, inv1 = 1.0f / l1r;
    #pragma unroll
    for (int ni = 0; ni < 16; ni++){
        int col = ni * 8 + 2 * l3;
        *(__half2*)(Og + (long long)(qr + rl) * HIDDEN + col) =
            __floats2half2_rn(Oa[ni][0] * inv0, Oa[ni][1] * inv0);
        *(__half2*)(Og + (long long)(qr + rl + 8) * HIDDEN + col) =
            __floats2half2_rn(Oa[ni][2] * inv1, Oa[ni][3] * inv1);
    }
}

// ---------------- transpose + fp16 ----------------
__global__ void transpose_h(const float* s0, __half* d0, const float* s1, __half* d1,
                            const float* s2, __half* d2, const float* s3, __half* d3,
                            int R, int C, int doInvf)
{
    __shared__ float t[32][33];
    const float* in; __half* out;
    switch (blockIdx.z){
        case 0:  in = s0; out = d0; break;
        case 1:  in = s1; out = d1; break;
        case 2:  in = s2; out = d2; break;
        default: in = s3; out = d3; break;
    }
    if (doInvf && blockIdx.x == 0 && blockIdx.y == 0 && blockIdx.z == 0){
        int f = threadIdx.y * 32 + threadIdx.x;
        if (f < 64) g_invf[f] = (float)exp(-(double)f * (log(500000.0) / 64.0));
    }
    int x  = blockIdx.x * 32 + threadIdx.x;
    int y0 = blockIdx.y * 32 + threadIdx.y;
    #pragma unroll
    for (int dy = 0; dy < 32; dy += 8)
        t[threadIdx.y + dy][threadIdx.x] = in[(long long)(y0 + dy) * C + x];
    __syncthreads();
    int ox  = blockIdx.y * 32 + threadIdx.x;
    int oy0 = blockIdx.x * 32 + threadIdx.y;
    #pragma unroll
    for (int dy = 0; dy < 32; dy += 8)
        out[(long long)(oy0 + dy) * R + ox] = __float2half_rn(t[threadIdx.x][threadIdx.y + dy]);
}

__global__ void rmsnorm_h(const float* __restrict__ X, const float* __restrict__ sc,
                          __half* __restrict__ O){
    long long base = (long long)blockIdx.x * HIDDEN;
    int tid = threadIdx.x;
    float v[8]; float ss = 0.f;
    #pragma unroll
    for (int i = 0; i < 8; i++){
        v[i] = X[base + tid + i * 256];
        ss += v[i] * v[i];
    }
    ss = blockReduceSum(ss);
    float r = rsqrtf(ss * (1.0f / (float)HIDDEN) + 1e-5f);
    #pragma unroll
    for (int i = 0; i < 8; i++){
        int c = tid + i * 256;
        O[base + c] = __float2half_rn(v[i] * r * sc[c]);
    }
}

// ---------------- launch ----------------
extern "C" void kernel_launch(void* const* d_in, const int* in_sizes, int n_in,
                              void* d_out, int out_size)
{
    const float* x   = (const float*)d_in[0];
    const int*   pos = (const int*)d_in[1];
    // d_in[2] = mask (causal; handled analytically)
    const float* wq  = (const float*)d_in[3];
    const float* wk  = (const float*)d_in[4];
    const float* wv  = (const float*)d_in[5];
    const float* wo  = (const float*)d_in[6];
    const float* asc = (const float*)d_in[7];
    const float* fsc = (const float*)d_in[8];
    const float* w1  = (const float*)d_in[9];
    const float* w3  = (const float*)d_in[10];
    const float* w2  = (const float*)d_in[11];
    float* out = (float*)d_out;

    __half *p_xnh,*p_qh,*p_kh,*p_vth,*p_aoh,*p_ffnh,*p_g1h;
    float *p_h;
    __half *p_wqkv,*p_wo,*p_w1,*p_w3,*p_w2;
    cudaGetSymbolAddress((void**)&p_xnh,  g_xnh);
    cudaGetSymbolAddress((void**)&p_qh,   g_qh);
    cudaGetSymbolAddress((void**)&p_kh,   g_kh);
    cudaGetSymbolAddress((void**)&p_vth,  g_vth);
    cudaGetSymbolAddress((void**)&p_aoh,  g_aoh);
    cudaGetSymbolAddress((void**)&p_h,    g_h);
    cudaGetSymbolAddress((void**)&p_ffnh, g_ffnh);
    cudaGetSymbolAddress((void**)&p_g1h,  g_g1h);
    cudaGetSymbolAddress((void**)&p_wqkv, g_wqkv);
    cudaGetSymbolAddress((void**)&p_wo,   g_wo);
    cudaGetSymbolAddress((void**)&p_w1,   g_w1);
    cudaGetSymbolAddress((void**)&p_w3,   g_w3);
    cudaGetSymbolAddress((void**)&p_w2,   g_w2);

    cudaFuncSetAttribute(gemm_h,   cudaFuncAttributeMaxDynamicSharedMemorySize, SMEM_H);
    cudaFuncSetAttribute(gemm_qkv, cudaFuncAttributeMaxDynamicSharedMemorySize, SMEM_H);
    cudaFuncSetAttribute(gemm_ff,  cudaFuncAttributeMaxDynamicSharedMemorySize, SMEM_F);
    cudaFuncSetAttribute(flash_h,  cudaFuncAttributeMaxDynamicSharedMemorySize, FLASH_SMEM);

    // 0. transpose + fp16 weights; wq|wk|wv concatenated into wqkv
    transpose_h<<<dim3(64,64,4), dim3(32,8)>>>(
        wq, p_wqkv,
        wk, p_wqkv + (size_t)HIDDEN*HIDDEN,
        wv, p_wqkv + (size_t)2*HIDDEN*HIDDEN,
        wo, p_wo, HIDDEN, HIDDEN, 1);
    transpose_h<<<dim3(176,64,2), dim3(32,8)>>>(w1,p_w1, w3,p_w3, nullptr,nullptr,
                                                nullptr,nullptr, HIDDEN, FFDIM, 0);
    transpose_h<<<dim3(64,176,1), dim3(32,8)>>>(w2,p_w2, nullptr,nullptr, nullptr,nullptr,
                                                nullptr,nullptr, FFDIM, HIDDEN, 0);

    // 1. rmsnorm (attn) -> fp16
    rmsnorm_h<<<NTOK,256>>>(x, asc, p_xnh);

    // 2. merged QKV projection (N=6144), rope->fp16 q/k, transposed fp16 v
    dim3 gQKV(32*48, 1, 1);
    gemm_qkv<<<gQKV,256,SMEM_H>>>(p_xnh,HIDDEN, p_wqkv,HIDDEN,
                                  p_qh, p_kh, p_vth, pos, HIDDEN, 32,48);

    // 3. flash attention (fp16, ldmatrix)
    flash_h<<<dim3(16, BATCHN*NHEADS),256,FLASH_SMEM>>>(
        p_qh, p_kh, p_vth, p_aoh, 0.08838834764831845f);

    // 4. h = x + attn_out @ wo
    dim3 gProj(32*16, 1, 1);
    gemm_h<<<gProj,256,SMEM_H>>>(p_aoh,HIDDEN, p_wo,HIDDEN, p_h,HIDDEN,
                                 x, HIDDEN, 32,16);

    // 5. rmsnorm (ffn) -> fp16
    rmsnorm_h<<<NTOK,256>>>(p_h, fsc, p_ffnh);

    // 6. fused FFN up+gate+silu -> g1h
    dim3 gFF(32*88, 1, 1);
    gemm_ff<<<gFF,256,SMEM_F>>>(p_ffnh,HIDDEN, p_w1,p_w3,HIDDEN, p_g1h,FFDIM,
                                HIDDEN, 32,88);

    // 7. out = h + g1h @ w2  (K = 5632)
    gemm_h<<<gProj,256,SMEM_H>>>(p_g1h,FFDIM, p_w2,FFDIM, out,HIDDEN,
                                 p_h, FFDIM, 32,16);
}